// round 1
// baseline (speedup 1.0000x reference)
#include <cuda_runtime.h>
#include <math.h>

// ---------------- static config ----------------
#define BB    8
#define HH    64
#define WW_   512
#define DIM_  128
#define HEADS 4
#define HD    32
#define WH_   4
#define WWIN  32
#define NTOK  128          // tokens per window
#define NHW   16
#define NWW   16
#define NWIN  256          // windows per image
#define NW    2048         // total windows (B * NWIN)
#define TOK   (BB*HH*WW_)  // 262144 tokens
#define FF    512
#define SHIFT 2
#define SCALE 0.17677669529663687f
#define PAD   132          // smem row pitch (floats), 16B aligned, conflict-free

// ---------------- scratch (device globals; no runtime alloc) ----------------
__device__ float g_q[NW*HEADS*NTOK*HD];
__device__ float g_k[NW*HEADS*NTOK*HD];
__device__ float g_v[NW*HEADS*NTOK*HD];
__device__ float g_o[NW*NTOK*DIM_];
__device__ float g_x1[TOK*DIM_];
__device__ float g_h[TOK*FF];

// ---------------- 128x128x128 register-blocked GEMM tile ----------------
// Xs: [k][m] pitch PAD ; Ws: [k][n] pitch PAD ; 256 threads, 8x8 per thread
__device__ __forceinline__ void gemm_tile(const float* __restrict__ Xs,
                                          const float* __restrict__ Ws,
                                          float acc[8][8], int tx, int ty) {
    #pragma unroll 4
    for (int k = 0; k < 128; k++) {
        float a[8], b[8];
        *(float4*)&a[0] = *(const float4*)&Xs[k*PAD + ty*8];
        *(float4*)&a[4] = *(const float4*)&Xs[k*PAD + ty*8 + 4];
        *(float4*)&b[0] = *(const float4*)&Ws[k*PAD + tx*8];
        *(float4*)&b[4] = *(const float4*)&Ws[k*PAD + tx*8 + 4];
        #pragma unroll
        for (int i = 0; i < 8; i++)
            #pragma unroll
            for (int j = 0; j < 8; j++)
                acc[i][j] += a[i]*b[j];
    }
}

// ---------------- kernel 1: LN1 + shift + window partition + QKV ----------------
__global__ __launch_bounds__(256) void k_ln_qkv(const float* __restrict__ x,
                                                const float* __restrict__ g1,
                                                const float* __restrict__ b1,
                                                const float* __restrict__ w,
                                                const float* __restrict__ bias) {
    extern __shared__ float sm[];
    float* Xs = sm;              // [128][PAD] transposed: [k][m]
    float* Ws = sm + 128*PAD;    // [128][PAD]
    const int win = blockIdx.x;
    const int b  = win >> 8;          // / NWIN
    const int wi = win & 255;
    const int wh = wi >> 4, ww = wi & 15;
    const int t = threadIdx.x;
    const int tx = t & 15, ty = t >> 4;

    // load x window (shifted) transposed into Xs[k][m]
    for (int idx = t; idx < 128*128; idx += 256) {
        int m = idx >> 7, k = idx & 127;
        int mi = m >> 5, mj = m & 31;
        int r = (wh*WH_ + mi + SHIFT) & (HH-1);
        int c = (ww*WWIN + mj + SHIFT) & (WW_-1);
        Xs[k*PAD + m] = x[((b*HH + r)*WW_ + c)*DIM_ + k];
    }
    __syncthreads();

    // layernorm per token (column of Xs)
    if (t < 128) {
        float s = 0.f, ss = 0.f;
        #pragma unroll 8
        for (int k = 0; k < 128; k++) { float v = Xs[k*PAD + t]; s += v; ss += v*v; }
        float mean = s * (1.f/128.f);
        float var  = ss * (1.f/128.f) - mean*mean;
        float rstd = rsqrtf(var + 1e-5f);
        #pragma unroll 4
        for (int k = 0; k < 128; k++)
            Xs[k*PAD + t] = (Xs[k*PAD + t] - mean)*rstd*g1[k] + b1[k];
    }
    __syncthreads();

    // 3 column tiles: q, k, v
    for (int ct = 0; ct < 3; ct++) {
        for (int idx = t; idx < 128*128; idx += 256) {
            int k = idx >> 7, n = idx & 127;
            Ws[k*PAD + n] = w[k*384 + ct*128 + n];
        }
        __syncthreads();
        float acc[8][8];
        #pragma unroll
        for (int i = 0; i < 8; i++)
            #pragma unroll
            for (int j = 0; j < 8; j++) acc[i][j] = 0.f;
        gemm_tile(Xs, Ws, acc, tx, ty);
        __syncthreads();

        float* dst = (ct == 0) ? g_q : (ct == 1 ? g_k : g_v);
        float scl  = (ct == 0) ? SCALE : 1.f;
        #pragma unroll
        for (int i = 0; i < 8; i++) {
            int m = ty*8 + i;
            #pragma unroll
            for (int j = 0; j < 8; j++) {
                int n = tx*8 + j;
                int h = n >> 5, d = n & 31;
                dst[((win*HEADS + h)*NTOK + m)*HD + d] =
                    (acc[i][j] + bias[ct*128 + n]) * scl;
            }
        }
    }
}

// ---------------- kernel 2: windowed attention ----------------
__global__ __launch_bounds__(128) void k_attn(const float* __restrict__ rpb) {
    extern __shared__ float sm[];
    float* qs = sm;                    // [128][33]
    float* ks = qs + 128*33;           // [128][36]
    float* vs = ks + 128*36;           // [128][36]
    float* at = vs + 128*36;           // [128][129]
    const int win = blockIdx.x, h = blockIdx.y;
    const int t = threadIdx.x;

    const float* qg = g_q + (win*HEADS + h)*NTOK*HD;
    const float* kg = g_k + (win*HEADS + h)*NTOK*HD;
    const float* vg = g_v + (win*HEADS + h)*NTOK*HD;
    for (int idx = t; idx < 128*32; idx += 128) {
        int r = idx >> 5, d = idx & 31;
        qs[r*33 + d] = qg[idx];
        ks[r*36 + d] = kg[idx];
        vs[r*36 + d] = vg[idx];
    }
    __syncthreads();

    const int wi = win & 255;
    const int wh = wi >> 4, ww = wi & 15;
    const int i = t, ih = i >> 5, iw = i & 31;
    const int rg_i = (wh < 15) ? 0 : ((ih < 2) ? 1 : 2);
    const int cg_i = (ww < 15) ? 0 : ((iw < 30) ? 1 : 2);
    const int cnt_i = rg_i*3 + cg_i;

    float q[32];
    #pragma unroll
    for (int d = 0; d < 32; d++) q[d] = qs[i*33 + d];

    float* arow = at + i*129;
    // phase A: scores + bias + mask
    #pragma unroll 2
    for (int j = 0; j < 128; j++) {
        const float4* kr = (const float4*)(ks + j*36);
        float s0 = 0.f, s1 = 0.f, s2 = 0.f, s3 = 0.f;
        #pragma unroll
        for (int d4 = 0; d4 < 8; d4++) {
            float4 kv = kr[d4];
            s0 += q[d4*4+0]*kv.x; s1 += q[d4*4+1]*kv.y;
            s2 += q[d4*4+2]*kv.z; s3 += q[d4*4+3]*kv.w;
        }
        float s = (s0 + s1) + (s2 + s3);
        int jh = j >> 5, jw = j & 31;
        int ridx = (ih - jh + 3)*63 + (iw - jw + 31);
        s += rpb[ridx*HEADS + h];
        int rg_j = (wh < 15) ? 0 : ((jh < 2) ? 1 : 2);
        int cg_j = (ww < 15) ? 0 : ((jw < 30) ? 1 : 2);
        if (rg_j*3 + cg_j != cnt_i) s -= 100.f;
        arow[j] = s;
    }
    // phase B: softmax + AV
    float mx = -1e30f;
    #pragma unroll 4
    for (int j = 0; j < 128; j++) mx = fmaxf(mx, arow[j]);
    float acc[32];
    #pragma unroll
    for (int d = 0; d < 32; d++) acc[d] = 0.f;
    float sum = 0.f;
    #pragma unroll 2
    for (int j = 0; j < 128; j++) {
        float p = __expf(arow[j] - mx);
        sum += p;
        const float4* vr = (const float4*)(vs + j*36);
        #pragma unroll
        for (int d4 = 0; d4 < 8; d4++) {
            float4 vv = vr[d4];
            acc[d4*4+0] += p*vv.x; acc[d4*4+1] += p*vv.y;
            acc[d4*4+2] += p*vv.z; acc[d4*4+3] += p*vv.w;
        }
    }
    float inv = 1.f / sum;
    float* og = g_o + (win*NTOK + i)*DIM_ + h*HD;
    #pragma unroll
    for (int d4 = 0; d4 < 8; d4++) {
        float4 o4;
        o4.x = acc[d4*4+0]*inv; o4.y = acc[d4*4+1]*inv;
        o4.z = acc[d4*4+2]*inv; o4.w = acc[d4*4+3]*inv;
        *(float4*)(og + d4*4) = o4;
    }
}

// ---------------- kernel 3: proj + window reverse + residual ----------------
__global__ __launch_bounds__(256) void k_proj(const float* __restrict__ x,
                                              const float* __restrict__ w,
                                              const float* __restrict__ bias) {
    extern __shared__ float sm[];
    float* Xs = sm;
    float* Ws = sm + 128*PAD;
    const int win = blockIdx.x;
    const int t = threadIdx.x;
    const int tx = t & 15, ty = t >> 4;

    for (int idx = t; idx < 128*128; idx += 256) {
        int m = idx >> 7, k = idx & 127;
        Xs[k*PAD + m] = g_o[(win*NTOK + m)*DIM_ + k];
    }
    for (int idx = t; idx < 128*128; idx += 256) {
        int k = idx >> 7, n = idx & 127;
        Ws[k*PAD + n] = w[k*DIM_ + n];
    }
    __syncthreads();
    float acc[8][8];
    #pragma unroll
    for (int i = 0; i < 8; i++)
        #pragma unroll
        for (int j = 0; j < 8; j++) acc[i][j] = 0.f;
    gemm_tile(Xs, Ws, acc, tx, ty);

    const int b = win >> 8, wi = win & 255;
    const int wh = wi >> 4, ww = wi & 15;
    #pragma unroll
    for (int i = 0; i < 8; i++) {
        int m = ty*8 + i;
        int mi = m >> 5, mj = m & 31;
        int r = (wh*WH_ + mi + SHIFT) & (HH-1);
        int c = (ww*WWIN + mj + SHIFT) & (WW_-1);
        int base = ((b*HH + r)*WW_ + c)*DIM_;
        #pragma unroll
        for (int j = 0; j < 8; j++) {
            int n = tx*8 + j;
            g_x1[base + n] = x[base + n] + acc[i][j] + bias[n];
        }
    }
}

// ---------------- kernel 4: LN2 + fc1 + exact GELU ----------------
__global__ __launch_bounds__(256) void k_mlp1(const float* __restrict__ g2,
                                              const float* __restrict__ b2,
                                              const float* __restrict__ w,
                                              const float* __restrict__ bias) {
    extern __shared__ float sm[];
    float* Xs = sm;
    float* Ws = sm + 128*PAD;
    const int tile = blockIdx.x;
    const int t = threadIdx.x;
    const int tx = t & 15, ty = t >> 4;
    const float* xt = g_x1 + (size_t)tile*128*DIM_;

    for (int idx = t; idx < 128*128; idx += 256) {
        int m = idx >> 7, k = idx & 127;
        Xs[k*PAD + m] = xt[m*DIM_ + k];
    }
    __syncthreads();
    if (t < 128) {
        float s = 0.f, ss = 0.f;
        #pragma unroll 8
        for (int k = 0; k < 128; k++) { float v = Xs[k*PAD + t]; s += v; ss += v*v; }
        float mean = s * (1.f/128.f);
        float var  = ss * (1.f/128.f) - mean*mean;
        float rstd = rsqrtf(var + 1e-5f);
        #pragma unroll 4
        for (int k = 0; k < 128; k++)
            Xs[k*PAD + t] = (Xs[k*PAD + t] - mean)*rstd*g2[k] + b2[k];
    }
    __syncthreads();

    for (int ct = 0; ct < 4; ct++) {
        for (int idx = t; idx < 128*128; idx += 256) {
            int k = idx >> 7, n = idx & 127;
            Ws[k*PAD + n] = w[k*FF + ct*128 + n];
        }
        __syncthreads();
        float acc[8][8];
        #pragma unroll
        for (int i = 0; i < 8; i++)
            #pragma unroll
            for (int j = 0; j < 8; j++) acc[i][j] = 0.f;
        gemm_tile(Xs, Ws, acc, tx, ty);
        __syncthreads();
        #pragma unroll
        for (int i = 0; i < 8; i++) {
            int m = ty*8 + i;
            #pragma unroll
            for (int j = 0; j < 8; j++) {
                int n = tx*8 + j;
                float v = acc[i][j] + bias[ct*128 + n];
                float g = 0.5f * v * (1.f + erff(v * 0.70710678118654752f));
                g_h[(size_t)(tile*128 + m)*FF + ct*128 + n] = g;
            }
        }
    }
}

// ---------------- kernel 5: fc2 + residual ----------------
__global__ __launch_bounds__(256) void k_mlp2(const float* __restrict__ w,
                                              const float* __restrict__ bias,
                                              float* __restrict__ out) {
    extern __shared__ float sm[];
    float* Xs = sm;
    float* Ws = sm + 128*PAD;
    const int tile = blockIdx.x;
    const int t = threadIdx.x;
    const int tx = t & 15, ty = t >> 4;

    float acc[8][8];
    #pragma unroll
    for (int i = 0; i < 8; i++)
        #pragma unroll
        for (int j = 0; j < 8; j++) acc[i][j] = 0.f;

    for (int kc = 0; kc < 4; kc++) {
        for (int idx = t; idx < 128*128; idx += 256) {
            int m = idx >> 7, k = idx & 127;
            Xs[k*PAD + m] = g_h[(size_t)(tile*128 + m)*FF + kc*128 + k];
        }
        for (int idx = t; idx < 128*128; idx += 256) {
            int k = idx >> 7, n = idx & 127;
            Ws[k*PAD + n] = w[(kc*128 + k)*DIM_ + n];
        }
        __syncthreads();
        gemm_tile(Xs, Ws, acc, tx, ty);
        __syncthreads();
    }
    const float* xr = g_x1 + (size_t)tile*128*DIM_;
    float* or_ = out + (size_t)tile*128*DIM_;
    #pragma unroll
    for (int i = 0; i < 8; i++) {
        int m = ty*8 + i;
        #pragma unroll
        for (int j = 0; j < 8; j++) {
            int n = tx*8 + j;
            or_[m*DIM_ + n] = xr[m*DIM_ + n] + acc[i][j] + bias[n];
        }
    }
}

// ---------------- launcher ----------------
extern "C" void kernel_launch(void* const* d_in, const int* in_sizes, int n_in,
                              void* d_out, int out_size) {
    (void)in_sizes; (void)n_in; (void)out_size;
    const float* x      = (const float*)d_in[0];
    const float* g1     = (const float*)d_in[1];
    const float* b1     = (const float*)d_in[2];
    const float* qkv_w  = (const float*)d_in[3];
    const float* qkv_b  = (const float*)d_in[4];
    const float* rpb    = (const float*)d_in[5];
    const float* proj_w = (const float*)d_in[6];
    const float* proj_b = (const float*)d_in[7];
    const float* g2     = (const float*)d_in[8];
    const float* b2     = (const float*)d_in[9];
    const float* fc1_w  = (const float*)d_in[10];
    const float* fc1_b  = (const float*)d_in[11];
    const float* fc2_w  = (const float*)d_in[12];
    const float* fc2_b  = (const float*)d_in[13];
    float* out = (float*)d_out;

    const int SM_GEMM = 2*128*PAD*(int)sizeof(float);                    // 135168 B
    const int SM_ATTN = (128*33 + 2*128*36 + 128*129)*(int)sizeof(float); // 119808 B

    cudaFuncSetAttribute(k_ln_qkv, cudaFuncAttributeMaxDynamicSharedMemorySize, SM_GEMM);
    cudaFuncSetAttribute(k_attn,   cudaFuncAttributeMaxDynamicSharedMemorySize, SM_ATTN);
    cudaFuncSetAttribute(k_proj,   cudaFuncAttributeMaxDynamicSharedMemorySize, SM_GEMM);
    cudaFuncSetAttribute(k_mlp1,   cudaFuncAttributeMaxDynamicSharedMemorySize, SM_GEMM);
    cudaFuncSetAttribute(k_mlp2,   cudaFuncAttributeMaxDynamicSharedMemorySize, SM_GEMM);

    k_ln_qkv<<<NW, 256, SM_GEMM>>>(x, g1, b1, qkv_w, qkv_b);
    k_attn<<<dim3(NW, HEADS), 128, SM_ATTN>>>(rpb);
    k_proj<<<NW, 256, SM_GEMM>>>(x, proj_w, proj_b);
    k_mlp1<<<TOK/128, 256, SM_GEMM>>>(g2, b2, fc1_w, fc1_b);
    k_mlp2<<<TOK/128, 256, SM_GEMM>>>(fc2_w, fc2_b, out);
}

// round 3
// speedup vs baseline: 5.5841x; 5.5841x over previous
#include <cuda_runtime.h>
#include <cuda_bf16.h>
#include <math.h>
#include <stdint.h>

// ---------------- static config ----------------
#define NW    2048
#define TOK   262144
#define FF    512
#define SHIFT 2
#define SCALE 0.17677669529663687f
#define PITCH 272          // smem row pitch in bytes (136 bf16) -> ldmatrix conflict-free

// ---------------- scratch ----------------
__device__ float g_q[NW*4*128*32];
__device__ float g_k[NW*4*128*32];
__device__ float g_v[NW*4*128*32];
__device__ float g_o[NW*128*128];
__device__ float g_x1[TOK*128];
__device__ __nv_bfloat16 g_h[(size_t)TOK*FF];

// ---------------- helpers ----------------
__device__ __forceinline__ uint32_t smem_u32(const void* p) {
    uint32_t a;
    asm("{ .reg .u64 t; cvta.to.shared.u64 t, %1; cvt.u32.u64 %0, t; }" : "=r"(a) : "l"(p));
    return a;
}

__device__ __forceinline__ void ldmx4(uint32_t* r, uint32_t addr) {
    asm volatile("ldmatrix.sync.aligned.m8n8.x4.shared.b16 {%0,%1,%2,%3}, [%4];"
        : "=r"(r[0]), "=r"(r[1]), "=r"(r[2]), "=r"(r[3]) : "r"(addr));
}

__device__ __forceinline__ void mma16816(float* c, const uint32_t* a, const uint32_t* b) {
    asm volatile("mma.sync.aligned.m16n8k16.row.col.f32.bf16.bf16.f32 "
        "{%0,%1,%2,%3}, {%4,%5,%6,%7}, {%8,%9}, {%0,%1,%2,%3};"
        : "+f"(c[0]), "+f"(c[1]), "+f"(c[2]), "+f"(c[3])
        : "r"(a[0]), "r"(a[1]), "r"(a[2]), "r"(a[3]), "r"(b[0]), "r"(b[1]));
}

// warp computes 64x32 of C over K=128. As: [m][k] bf16 pitch PITCH; Bs: [n][k].
__device__ __forceinline__ void warp_mma_tile(uint32_t As, uint32_t Bs,
                                              float acc[4][4][4],
                                              int warp_m, int warp_n, int lane) {
    const int ar = (lane & 7) + ((lane >> 3) & 1) * 8;
    const int ak = ((lane >> 4) & 1) * 16;
    const int br = (lane & 7) + ((lane >> 4) & 1) * 8;
    const int bk = ((lane >> 3) & 1) * 16;
    const uint32_t a_base = As + (warp_m * 64 + ar) * PITCH + ak;
    const uint32_t b_base = Bs + (warp_n * 32 + br) * PITCH + bk;
    #pragma unroll
    for (int ks = 0; ks < 8; ks++) {
        uint32_t af[4][4], bf[2][4];
        #pragma unroll
        for (int mt = 0; mt < 4; mt++) ldmx4(af[mt], a_base + mt * 16 * PITCH + ks * 32);
        #pragma unroll
        for (int np = 0; np < 2; np++) ldmx4(bf[np], b_base + np * 16 * PITCH + ks * 32);
        #pragma unroll
        for (int mt = 0; mt < 4; mt++) {
            mma16816(acc[mt][0], af[mt], &bf[0][0]);
            mma16816(acc[mt][1], af[mt], &bf[0][2]);
            mma16816(acc[mt][2], af[mt], &bf[1][0]);
            mma16816(acc[mt][3], af[mt], &bf[1][2]);
        }
    }
}

#define ZERO_ACC(acc) do { \
    _Pragma("unroll") for (int _i = 0; _i < 4; _i++) \
    _Pragma("unroll") for (int _j = 0; _j < 4; _j++) \
    _Pragma("unroll") for (int _k = 0; _k < 4; _k++) acc[_i][_j][_k] = 0.f; } while (0)

// ============== kernel 1: LN1 + shift + window partition + QKV ==============
__global__ __launch_bounds__(256) void k_ln_qkv(const float* __restrict__ x,
                                                const float* __restrict__ g1,
                                                const float* __restrict__ b1,
                                                const float* __restrict__ w,
                                                const float* __restrict__ bias) {
    extern __shared__ char smc[];
    char* Asm = smc;
    char* Bsm = smc + 128 * PITCH;
    const uint32_t As = smem_u32(Asm), Bs = smem_u32(Bsm);
    const int win = blockIdx.x;
    const int b = win >> 8, wi = win & 255, wh = wi >> 4, ww = wi & 15;
    const int t = threadIdx.x, lane = t & 31, wid = t >> 5;
    const int warp_m = wid >> 2, warp_n = wid & 3;

    // load shifted window tokens (coalesced float4) -> bf16 A tile (raw)
    for (int i = t; i < 4096; i += 256) {
        int m = i >> 5, k4 = i & 31;
        int r = (wh * 4 + (m >> 5) + SHIFT) & 63;
        int c = (ww * 32 + (m & 31) + SHIFT) & 511;
        float4 v = *(const float4*)(x + (((size_t)(b * 64 + r) * 512 + c) * 128 + k4 * 4));
        __nv_bfloat162* d = (__nv_bfloat162*)(Asm + m * PITCH + k4 * 8);
        d[0] = __floats2bfloat162_rn(v.x, v.y);
        d[1] = __floats2bfloat162_rn(v.z, v.w);
    }
    __syncthreads();
    // LN in place (thread t owns token row t)
    if (t < 128) {
        __nv_bfloat16* row = (__nv_bfloat16*)(Asm + t * PITCH);
        float s = 0.f, ss = 0.f;
        #pragma unroll 8
        for (int k = 0; k < 128; k++) { float v = __bfloat162float(row[k]); s += v; ss += v * v; }
        float mean = s * (1.f / 128.f);
        float rstd = rsqrtf(ss * (1.f / 128.f) - mean * mean + 1e-5f);
        #pragma unroll 4
        for (int k = 0; k < 128; k += 2) {
            float v0 = (__bfloat162float(row[k]) - mean) * rstd * g1[k] + b1[k];
            float v1 = (__bfloat162float(row[k + 1]) - mean) * rstd * g1[k + 1] + b1[k + 1];
            *(__nv_bfloat162*)(row + k) = __floats2bfloat162_rn(v0, v1);
        }
    }
    __syncthreads();

    for (int ct = 0; ct < 3; ct++) {
        // B tile: [n][k] from w[k][384] column ct*128+n  (coalesced over n)
        for (int i = t; i < 8192; i += 256) {
            int n = i & 127, k2 = i >> 7;
            float v0 = w[(size_t)(2 * k2) * 384 + ct * 128 + n];
            float v1 = w[(size_t)(2 * k2 + 1) * 384 + ct * 128 + n];
            *(__nv_bfloat162*)(Bsm + n * PITCH + k2 * 4) = __floats2bfloat162_rn(v0, v1);
        }
        __syncthreads();
        float acc[4][4][4];
        ZERO_ACC(acc);
        warp_mma_tile(As, Bs, acc, warp_m, warp_n, lane);

        float* dst = (ct == 0) ? g_q : ((ct == 1) ? g_k : g_v);
        const float scl = (ct == 0) ? SCALE : 1.f;
        // head = warp_n (cols warp_n*32..+31)
        float* hb = dst + (((size_t)win * 4 + warp_n) * 128) * 32;
        #pragma unroll
        for (int mt = 0; mt < 4; mt++) {
            int row0 = warp_m * 64 + mt * 16 + (lane >> 2);
            #pragma unroll
            for (int j = 0; j < 4; j++) {
                int d = j * 8 + (lane & 3) * 2;
                float2 v0, v1;
                v0.x = (acc[mt][j][0] + bias[ct * 128 + warp_n * 32 + d]) * scl;
                v0.y = (acc[mt][j][1] + bias[ct * 128 + warp_n * 32 + d + 1]) * scl;
                v1.x = (acc[mt][j][2] + bias[ct * 128 + warp_n * 32 + d]) * scl;
                v1.y = (acc[mt][j][3] + bias[ct * 128 + warp_n * 32 + d + 1]) * scl;
                *(float2*)(hb + (size_t)row0 * 32 + d) = v0;
                *(float2*)(hb + (size_t)(row0 + 8) * 32 + d) = v1;
            }
        }
        __syncthreads();
    }
}

// ============== kernel 2: windowed attention (fp32 SIMT, 1-pass, no max) ==============
__global__ __launch_bounds__(128) void k_attn(const float* __restrict__ rpb) {
    extern __shared__ float sm[];
    float* qs = sm;                 // [128][33]
    float* ks = sm + 128 * 33;      // [128][36]
    float* vs = ks + 128 * 36;      // [128][36]
    float* bs = vs + 128 * 36;      // [448]
    const int win = blockIdx.x, h = blockIdx.y, t = threadIdx.x;

    const float* qg = g_q + ((size_t)win * 4 + h) * 128 * 32;
    const float* kg = g_k + ((size_t)win * 4 + h) * 128 * 32;
    const float* vg = g_v + ((size_t)win * 4 + h) * 128 * 32;
    for (int idx = t; idx < 128 * 32; idx += 128) {
        int r = idx >> 5, d = idx & 31;
        qs[r * 33 + d] = qg[idx];
        ks[r * 36 + d] = kg[idx];
        vs[r * 36 + d] = vg[idx];
    }
    for (int idx = t; idx < 441; idx += 128) bs[idx] = rpb[idx * 4 + h];
    __syncthreads();

    const int wi = win & 255, wh = wi >> 4, ww = wi & 15;
    const int ih = t >> 5, iw = t & 31;
    const int grpi = ((wh < 15) ? 0 : ((ih < 2) ? 1 : 2)) * 3
                   + ((ww < 15) ? 0 : ((iw < 30) ? 1 : 2));
    const int ibase = ih * 63 + iw + 220;

    float q[32];
    #pragma unroll
    for (int d = 0; d < 32; d++) q[d] = qs[t * 33 + d];

    float acc[32];
    #pragma unroll
    for (int d = 0; d < 32; d++) acc[d] = 0.f;
    float sum = 0.f;
    #pragma unroll 2
    for (int j = 0; j < 128; j++) {
        const float4* kr = (const float4*)(ks + j * 36);
        float s0 = 0.f, s1 = 0.f, s2 = 0.f, s3 = 0.f;
        #pragma unroll
        for (int d4 = 0; d4 < 8; d4++) {
            float4 kv = kr[d4];
            s0 += q[d4 * 4 + 0] * kv.x; s1 += q[d4 * 4 + 1] * kv.y;
            s2 += q[d4 * 4 + 2] * kv.z; s3 += q[d4 * 4 + 3] * kv.w;
        }
        int jh = j >> 5, jw = j & 31;
        float s = (s0 + s1) + (s2 + s3) + bs[ibase - (jh * 63 + jw)];
        int grpj = ((wh < 15) ? 0 : ((jh < 2) ? 1 : 2)) * 3
                 + ((ww < 15) ? 0 : ((jw < 30) ? 1 : 2));
        if (grpj != grpi) s -= 100.f;
        float p = __expf(s);           // scores bounded, masked -> underflow to 0
        sum += p;
        const float4* vr = (const float4*)(vs + j * 36);
        #pragma unroll
        for (int d4 = 0; d4 < 8; d4++) {
            float4 vv = vr[d4];
            acc[d4 * 4 + 0] += p * vv.x; acc[d4 * 4 + 1] += p * vv.y;
            acc[d4 * 4 + 2] += p * vv.z; acc[d4 * 4 + 3] += p * vv.w;
        }
    }
    float inv = 1.f / sum;
    float* og = g_o + ((size_t)win * 128 + t) * 128 + h * 32;
    #pragma unroll
    for (int d4 = 0; d4 < 8; d4++) {
        float4 o4;
        o4.x = acc[d4 * 4 + 0] * inv; o4.y = acc[d4 * 4 + 1] * inv;
        o4.z = acc[d4 * 4 + 2] * inv; o4.w = acc[d4 * 4 + 3] * inv;
        *(float4*)(og + d4 * 4) = o4;
    }
}

// ============== kernel 3: proj + window reverse + residual ==============
__global__ __launch_bounds__(256) void k_proj(const float* __restrict__ x,
                                              const float* __restrict__ w,
                                              const float* __restrict__ bias) {
    extern __shared__ char smc[];
    char* Asm = smc;
    char* Bsm = smc + 128 * PITCH;
    const uint32_t As = smem_u32(Asm), Bs = smem_u32(Bsm);
    const int win = blockIdx.x;
    const int b = win >> 8, wi = win & 255, wh = wi >> 4, ww = wi & 15;
    const int t = threadIdx.x, lane = t & 31, wid = t >> 5;
    const int warp_m = wid >> 2, warp_n = wid & 3;

    for (int i = t; i < 4096; i += 256) {
        int m = i >> 5, k4 = i & 31;
        float4 v = *(const float4*)(g_o + ((size_t)win * 128 + m) * 128 + k4 * 4);
        __nv_bfloat162* d = (__nv_bfloat162*)(Asm + m * PITCH + k4 * 8);
        d[0] = __floats2bfloat162_rn(v.x, v.y);
        d[1] = __floats2bfloat162_rn(v.z, v.w);
    }
    for (int i = t; i < 8192; i += 256) {
        int n = i & 127, k2 = i >> 7;
        float v0 = w[(size_t)(2 * k2) * 128 + n];
        float v1 = w[(size_t)(2 * k2 + 1) * 128 + n];
        *(__nv_bfloat162*)(Bsm + n * PITCH + k2 * 4) = __floats2bfloat162_rn(v0, v1);
    }
    __syncthreads();
    float acc[4][4][4];
    ZERO_ACC(acc);
    warp_mma_tile(As, Bs, acc, warp_m, warp_n, lane);

    #pragma unroll
    for (int mt = 0; mt < 4; mt++) {
        #pragma unroll
        for (int half = 0; half < 2; half++) {
            int row = warp_m * 64 + mt * 16 + (lane >> 2) + half * 8;
            int r = (wh * 4 + (row >> 5) + SHIFT) & 63;
            int c = (ww * 32 + (row & 31) + SHIFT) & 511;
            size_t base = ((size_t)(b * 64 + r) * 512 + c) * 128;
            #pragma unroll
            for (int j = 0; j < 4; j++) {
                int n = warp_n * 32 + j * 8 + (lane & 3) * 2;
                float2 xr = *(const float2*)(x + base + n);
                float2 v;
                v.x = xr.x + acc[mt][j][half * 2 + 0] + bias[n];
                v.y = xr.y + acc[mt][j][half * 2 + 1] + bias[n + 1];
                *(float2*)(g_x1 + base + n) = v;
            }
        }
    }
}

// ============== kernel 4: LN2 + fc1 + GELU ==============
__global__ __launch_bounds__(256) void k_mlp1(const float* __restrict__ g2,
                                              const float* __restrict__ b2,
                                              const float* __restrict__ w,
                                              const float* __restrict__ bias) {
    extern __shared__ char smc[];
    char* Asm = smc;
    char* Bsm = smc + 128 * PITCH;
    const uint32_t As = smem_u32(Asm), Bs = smem_u32(Bsm);
    const int tile = blockIdx.x;
    const int t = threadIdx.x, lane = t & 31, wid = t >> 5;
    const int warp_m = wid >> 2, warp_n = wid & 3;

    for (int i = t; i < 4096; i += 256) {
        int m = i >> 5, k4 = i & 31;
        float4 v = *(const float4*)(g_x1 + ((size_t)tile * 128 + m) * 128 + k4 * 4);
        __nv_bfloat162* d = (__nv_bfloat162*)(Asm + m * PITCH + k4 * 8);
        d[0] = __floats2bfloat162_rn(v.x, v.y);
        d[1] = __floats2bfloat162_rn(v.z, v.w);
    }
    __syncthreads();
    if (t < 128) {
        __nv_bfloat16* row = (__nv_bfloat16*)(Asm + t * PITCH);
        float s = 0.f, ss = 0.f;
        #pragma unroll 8
        for (int k = 0; k < 128; k++) { float v = __bfloat162float(row[k]); s += v; ss += v * v; }
        float mean = s * (1.f / 128.f);
        float rstd = rsqrtf(ss * (1.f / 128.f) - mean * mean + 1e-5f);
        #pragma unroll 4
        for (int k = 0; k < 128; k += 2) {
            float v0 = (__bfloat162float(row[k]) - mean) * rstd * g2[k] + b2[k];
            float v1 = (__bfloat162float(row[k + 1]) - mean) * rstd * g2[k + 1] + b2[k + 1];
            *(__nv_bfloat162*)(row + k) = __floats2bfloat162_rn(v0, v1);
        }
    }
    __syncthreads();

    for (int ct = 0; ct < 4; ct++) {
        for (int i = t; i < 8192; i += 256) {
            int n = i & 127, k2 = i >> 7;
            float v0 = w[(size_t)(2 * k2) * FF + ct * 128 + n];
            float v1 = w[(size_t)(2 * k2 + 1) * FF + ct * 128 + n];
            *(__nv_bfloat162*)(Bsm + n * PITCH + k2 * 4) = __floats2bfloat162_rn(v0, v1);
        }
        __syncthreads();
        float acc[4][4][4];
        ZERO_ACC(acc);
        warp_mma_tile(As, Bs, acc, warp_m, warp_n, lane);

        #pragma unroll
        for (int mt = 0; mt < 4; mt++) {
            #pragma unroll
            for (int half = 0; half < 2; half++) {
                int row = warp_m * 64 + mt * 16 + (lane >> 2) + half * 8;
                __nv_bfloat16* orow = g_h + ((size_t)tile * 128 + row) * FF + ct * 128;
                #pragma unroll
                for (int j = 0; j < 4; j++) {
                    int n = warp_n * 32 + j * 8 + (lane & 3) * 2;
                    float v0 = acc[mt][j][half * 2 + 0] + bias[ct * 128 + n];
                    float v1 = acc[mt][j][half * 2 + 1] + bias[ct * 128 + n + 1];
                    float e0 = 0.5f * v0 * (1.f + erff(v0 * 0.70710678118654752f));
                    float e1 = 0.5f * v1 * (1.f + erff(v1 * 0.70710678118654752f));
                    *(__nv_bfloat162*)(orow + n) = __floats2bfloat162_rn(e0, e1);
                }
            }
        }
        __syncthreads();
    }
}

// ============== kernel 5: fc2 + residual (K=512 in 4 chunks) ==============
__global__ __launch_bounds__(256) void k_mlp2(const float* __restrict__ w,
                                              const float* __restrict__ bias,
                                              float* __restrict__ out) {
    extern __shared__ char smc[];
    char* Asm = smc;
    char* Bsm = smc + 128 * PITCH;
    const uint32_t As = smem_u32(Asm), Bs = smem_u32(Bsm);
    const int tile = blockIdx.x;
    const int t = threadIdx.x, lane = t & 31, wid = t >> 5;
    const int warp_m = wid >> 2, warp_n = wid & 3;

    float acc[4][4][4];
    ZERO_ACC(acc);
    for (int kc = 0; kc < 4; kc++) {
        for (int i = t; i < 2048; i += 256) {
            int m = i >> 4, c16 = i & 15;
            uint4 u = *(const uint4*)(g_h + ((size_t)tile * 128 + m) * FF + kc * 128 + c16 * 8);
            *(uint4*)(Asm + m * PITCH + c16 * 16) = u;
        }
        for (int i = t; i < 8192; i += 256) {
            int n = i & 127, k2 = i >> 7;
            float v0 = w[(size_t)(kc * 128 + 2 * k2) * 128 + n];
            float v1 = w[(size_t)(kc * 128 + 2 * k2 + 1) * 128 + n];
            *(__nv_bfloat162*)(Bsm + n * PITCH + k2 * 4) = __floats2bfloat162_rn(v0, v1);
        }
        __syncthreads();
        warp_mma_tile(As, Bs, acc, warp_m, warp_n, lane);
        __syncthreads();
    }

    #pragma unroll
    for (int mt = 0; mt < 4; mt++) {
        #pragma unroll
        for (int half = 0; half < 2; half++) {
            int row = warp_m * 64 + mt * 16 + (lane >> 2) + half * 8;
            const float* xr = g_x1 + ((size_t)tile * 128 + row) * 128;
            float* orow = out + ((size_t)tile * 128 + row) * 128;
            #pragma unroll
            for (int j = 0; j < 4; j++) {
                int n = warp_n * 32 + j * 8 + (lane & 3) * 2;
                float2 rv = *(const float2*)(xr + n);
                float2 v;
                v.x = rv.x + acc[mt][j][half * 2 + 0] + bias[n];
                v.y = rv.y + acc[mt][j][half * 2 + 1] + bias[n + 1];
                *(float2*)(orow + n) = v;
            }
        }
    }
}

// ---------------- launcher ----------------
extern "C" void kernel_launch(void* const* d_in, const int* in_sizes, int n_in,
                              void* d_out, int out_size) {
    (void)in_sizes; (void)n_in; (void)out_size;
    const float* x      = (const float*)d_in[0];
    const float* g1     = (const float*)d_in[1];
    const float* b1     = (const float*)d_in[2];
    const float* qkv_w  = (const float*)d_in[3];
    const float* qkv_b  = (const float*)d_in[4];
    const float* rpb    = (const float*)d_in[5];
    const float* proj_w = (const float*)d_in[6];
    const float* proj_b = (const float*)d_in[7];
    const float* g2     = (const float*)d_in[8];
    const float* b2     = (const float*)d_in[9];
    const float* fc1_w  = (const float*)d_in[10];
    const float* fc1_b  = (const float*)d_in[11];
    const float* fc2_w  = (const float*)d_in[12];
    const float* fc2_b  = (const float*)d_in[13];
    float* out = (float*)d_out;

    const int SM_GEMM = 2 * 128 * PITCH;                        // 69632
    const int SM_ATTN = (128 * 33 + 128 * 36 * 2 + 448) * 4;    // 55552

    cudaFuncSetAttribute(k_ln_qkv, cudaFuncAttributeMaxDynamicSharedMemorySize, SM_GEMM);
    cudaFuncSetAttribute(k_attn,   cudaFuncAttributeMaxDynamicSharedMemorySize, SM_ATTN);
    cudaFuncSetAttribute(k_proj,   cudaFuncAttributeMaxDynamicSharedMemorySize, SM_GEMM);
    cudaFuncSetAttribute(k_mlp1,   cudaFuncAttributeMaxDynamicSharedMemorySize, SM_GEMM);
    cudaFuncSetAttribute(k_mlp2,   cudaFuncAttributeMaxDynamicSharedMemorySize, SM_GEMM);

    k_ln_qkv<<<NW, 256, SM_GEMM>>>(x, g1, b1, qkv_w, qkv_b);
    k_attn<<<dim3(NW, 4), 128, SM_ATTN>>>(rpb);
    k_proj<<<NW, 256, SM_GEMM>>>(x, proj_w, proj_b);
    k_mlp1<<<TOK / 128, 256, SM_GEMM>>>(g2, b2, fc1_w, fc1_b);
    k_mlp2<<<TOK / 128, 256, SM_GEMM>>>(fc2_w, fc2_b, out);
}

// round 4
// speedup vs baseline: 8.6788x; 1.5542x over previous
#include <cuda_runtime.h>
#include <cuda_bf16.h>
#include <math.h>
#include <stdint.h>

// ---------------- static config ----------------
#define NWTOT 2048
#define TOK   262144
#define SHIFT 2
#define SCALE 0.17677669529663687f
#define PITCH 272          // smem row pitch bytes (136 bf16), ldmatrix conflict-free

// ---------------- scratch ----------------
__device__ float g_x1[(size_t)TOK*128];
__device__ __nv_bfloat16 g_wq[384*128];   // qkv_w transposed [n][k]
__device__ __nv_bfloat16 g_wp[128*128];   // proj_w [n][k]
__device__ __nv_bfloat16 g_w1[512*128];   // fc1_w [n][k]
__device__ __nv_bfloat16 g_w2[128*512];   // fc2_w [n][k]

// ---------------- helpers ----------------
__device__ __forceinline__ uint32_t smem_u32(const void* p) {
    uint32_t a;
    asm("{ .reg .u64 t; cvta.to.shared.u64 t, %1; cvt.u32.u64 %0, t; }" : "=r"(a) : "l"(p));
    return a;
}
__device__ __forceinline__ void ldmx4(uint32_t* r, uint32_t addr) {
    asm volatile("ldmatrix.sync.aligned.m8n8.x4.shared.b16 {%0,%1,%2,%3}, [%4];"
        : "=r"(r[0]), "=r"(r[1]), "=r"(r[2]), "=r"(r[3]) : "r"(addr));
}
__device__ __forceinline__ void mma16816(float* c, const uint32_t* a, const uint32_t* b) {
    asm volatile("mma.sync.aligned.m16n8k16.row.col.f32.bf16.bf16.f32 "
        "{%0,%1,%2,%3}, {%4,%5,%6,%7}, {%8,%9}, {%0,%1,%2,%3};"
        : "+f"(c[0]), "+f"(c[1]), "+f"(c[2]), "+f"(c[3])
        : "r"(a[0]), "r"(a[1]), "r"(a[2]), "r"(a[3]), "r"(b[0]), "r"(b[1]));
}

// warp computes 64x32 of C over K=128. A: [m][k] pitch apitch; B: [n][k] pitch PITCH.
__device__ __forceinline__ void warp_mma_tile_p(uint32_t As, int apitch, uint32_t Bs,
                                                float acc[4][4][4],
                                                int warp_m, int warp_n, int lane) {
    const int ar = (lane & 7) + ((lane >> 3) & 1) * 8;
    const int ak = ((lane >> 4) & 1) * 16;
    const int br = (lane & 7) + ((lane >> 4) & 1) * 8;
    const int bk = ((lane >> 3) & 1) * 16;
    const uint32_t a_base = As + (warp_m * 64 + ar) * apitch + ak;
    const uint32_t b_base = Bs + (warp_n * 32 + br) * PITCH + bk;
    #pragma unroll
    for (int ks = 0; ks < 8; ks++) {
        uint32_t af[4][4], bf[2][4];
        #pragma unroll
        for (int mt = 0; mt < 4; mt++) ldmx4(af[mt], a_base + mt * 16 * apitch + ks * 32);
        #pragma unroll
        for (int np = 0; np < 2; np++) ldmx4(bf[np], b_base + np * 16 * PITCH + ks * 32);
        #pragma unroll
        for (int mt = 0; mt < 4; mt++) {
            mma16816(acc[mt][0], af[mt], &bf[0][0]);
            mma16816(acc[mt][1], af[mt], &bf[0][2]);
            mma16816(acc[mt][2], af[mt], &bf[1][0]);
            mma16816(acc[mt][3], af[mt], &bf[1][2]);
        }
    }
}

#define ZERO_ACC(acc) do { \
    _Pragma("unroll") for (int _i = 0; _i < 4; _i++) \
    _Pragma("unroll") for (int _j = 0; _j < 4; _j++) \
    _Pragma("unroll") for (int _k = 0; _k < 4; _k++) acc[_i][_j][_k] = 0.f; } while (0)

// ============== kernel 0: weight pre-conversion to bf16 [n][k] ==============
__global__ __launch_bounds__(256) void k_prep(const float* __restrict__ qkv_w,
                                              const float* __restrict__ proj_w,
                                              const float* __restrict__ fc1_w,
                                              const float* __restrict__ fc2_w) {
    int e = blockIdx.x * 256 + threadIdx.x;   // 0..65535
    if (e < 49152) {
        int n = e >> 7, k = e & 127;
        g_wq[e] = __float2bfloat16(qkv_w[(size_t)k * 384 + n]);
    }
    if (e < 16384) {
        int n = e >> 7, k = e & 127;
        g_wp[e] = __float2bfloat16(proj_w[(size_t)k * 128 + n]);
    }
    if (e < 65536) {
        {   // fc1: [512][128]
            int n = e >> 7, k = e & 127;
            g_w1[e] = __float2bfloat16(fc1_w[(size_t)k * 512 + n]);
        }
        {   // fc2: [128][512]
            int n = e >> 9, k = e & 511;
            g_w2[e] = __float2bfloat16(fc2_w[(size_t)k * 128 + n]);
        }
    }
}

// smem offsets for k_wmsa (bytes)
#define SM_QS 0
#define SM_KS 34816
#define SM_VT 69632
#define SM_OS 104448
#define SM_XP 139264      // Xs (LN'd x) then Ps (attention probs)
#define SM_WB 174080
#define SM_BI 208896      // bias float[4][448]
#define SM_WMSA 216064

// ============== kernel 1: fused W-MSA (LN1 + QKV + attn + proj + residual) ==============
__global__ __launch_bounds__(256) void k_wmsa(const float* __restrict__ x,
                                              const float* __restrict__ g1,
                                              const float* __restrict__ b1,
                                              const float* __restrict__ qkv_b,
                                              const float* __restrict__ rpb,
                                              const float* __restrict__ proj_b) {
    extern __shared__ char smc[];
    const uint32_t sb = smem_u32(smc);
    const int win = blockIdx.x;
    const int b = win >> 8, wi = win & 255, wh = wi >> 4, ww = wi & 15;
    const int t = threadIdx.x, lane = t & 31, wid = t >> 5;
    float* bsm = (float*)(smc + SM_BI);

    // --- load shifted window tokens -> Xs bf16 [m][k] ---
    for (int i = t; i < 4096; i += 256) {
        int m = i >> 5, k4 = i & 31;
        int r = (wh * 4 + (m >> 5) + SHIFT) & 63;
        int c = (ww * 32 + (m & 31) + SHIFT) & 511;
        float4 v = *(const float4*)(x + (((size_t)(b * 64 + r) * 512 + c) * 128 + k4 * 4));
        __nv_bfloat162* d = (__nv_bfloat162*)(smc + SM_XP + m * PITCH + k4 * 8);
        d[0] = __floats2bfloat162_rn(v.x, v.y);
        d[1] = __floats2bfloat162_rn(v.z, v.w);
    }
    // relative-position bias, per head: bsm[h][idx]
    for (int i = t; i < 1764; i += 256) bsm[(i & 3) * 448 + (i >> 2)] = rpb[i];
    __syncthreads();

    // --- LN1 in place ---
    if (t < 128) {
        __nv_bfloat16* row = (__nv_bfloat16*)(smc + SM_XP + t * PITCH);
        float s = 0.f, ss = 0.f;
        #pragma unroll 8
        for (int k = 0; k < 128; k++) { float v = __bfloat162float(row[k]); s += v; ss += v * v; }
        float mean = s * (1.f / 128.f);
        float rstd = rsqrtf(ss * (1.f / 128.f) - mean * mean + 1e-5f);
        #pragma unroll 4
        for (int k = 0; k < 128; k += 2) {
            float v0 = (__bfloat162float(row[k]) - mean) * rstd * g1[k] + b1[k];
            float v1 = (__bfloat162float(row[k + 1]) - mean) * rstd * g1[k + 1] + b1[k + 1];
            *(__nv_bfloat162*)(row + k) = __floats2bfloat162_rn(v0, v1);
        }
    }
    __syncthreads();

    // --- QKV GEMMs ---
    const int warp_m = wid >> 2, warp_n = wid & 3;
    for (int ct = 0; ct < 3; ct++) {
        for (int i = t; i < 2048; i += 256) {
            int n = i >> 4, c16 = i & 15;
            uint4 u = *(const uint4*)(g_wq + (size_t)(ct * 128 + n) * 128 + c16 * 8);
            *(uint4*)(smc + SM_WB + n * PITCH + c16 * 16) = u;
        }
        __syncthreads();
        float acc[4][4][4];
        ZERO_ACC(acc);
        warp_mma_tile_p(sb + SM_XP, PITCH, sb + SM_WB, acc, warp_m, warp_n, lane);

        #pragma unroll
        for (int mt = 0; mt < 4; mt++) {
            int row0 = warp_m * 64 + mt * 16 + (lane >> 2);
            int row1 = row0 + 8;
            #pragma unroll
            for (int j = 0; j < 4; j++) {
                int col = warp_n * 32 + j * 8 + (lane & 3) * 2;
                float b0 = qkv_b[ct * 128 + col], b1v = qkv_b[ct * 128 + col + 1];
                if (ct == 0) {
                    *(__nv_bfloat162*)(smc + SM_QS + row0 * PITCH + col * 2) =
                        __floats2bfloat162_rn((acc[mt][j][0] + b0) * SCALE, (acc[mt][j][1] + b1v) * SCALE);
                    *(__nv_bfloat162*)(smc + SM_QS + row1 * PITCH + col * 2) =
                        __floats2bfloat162_rn((acc[mt][j][2] + b0) * SCALE, (acc[mt][j][3] + b1v) * SCALE);
                } else if (ct == 1) {
                    *(__nv_bfloat162*)(smc + SM_KS + row0 * PITCH + col * 2) =
                        __floats2bfloat162_rn(acc[mt][j][0] + b0, acc[mt][j][1] + b1v);
                    *(__nv_bfloat162*)(smc + SM_KS + row1 * PITCH + col * 2) =
                        __floats2bfloat162_rn(acc[mt][j][2] + b0, acc[mt][j][3] + b1v);
                } else {
                    // V transposed: Vt[dim][token]
                    *(__nv_bfloat16*)(smc + SM_VT + col * PITCH + row0 * 2)       = __float2bfloat16(acc[mt][j][0] + b0);
                    *(__nv_bfloat16*)(smc + SM_VT + (col + 1) * PITCH + row0 * 2) = __float2bfloat16(acc[mt][j][1] + b1v);
                    *(__nv_bfloat16*)(smc + SM_VT + col * PITCH + row1 * 2)       = __float2bfloat16(acc[mt][j][2] + b0);
                    *(__nv_bfloat16*)(smc + SM_VT + (col + 1) * PITCH + row1 * 2) = __float2bfloat16(acc[mt][j][3] + b1v);
                }
            }
        }
        __syncthreads();
    }

    // --- attention: per head, MMA S=QK^T, softmax (no max), MMA O=PV ---
    const int g = wid;                       // warp owns rows 16g..16g+15
    const int ar = (lane & 7) + ((lane >> 3) & 1) * 8;
    const int ak = ((lane >> 4) & 1) * 16;
    const int br = (lane & 7) + ((lane >> 4) & 1) * 8;
    const int bk = ((lane >> 3) & 1) * 16;
    const int row0 = 16 * g + (lane >> 2), row1 = row0 + 8;
    const int rgrp0 = ((wh < 15) ? 0 : (((row0 >> 5) < 2) ? 1 : 2)) * 3
                    + ((ww < 15) ? 0 : (((row0 & 31) < 30) ? 1 : 2));
    const int rgrp1 = ((wh < 15) ? 0 : (((row1 >> 5) < 2) ? 1 : 2)) * 3
                    + ((ww < 15) ? 0 : (((row1 & 31) < 30) ? 1 : 2));
    const int ib0 = (row0 >> 5) * 63 + (row0 & 31) + 220;
    const int ib1 = (row1 >> 5) * 63 + (row1 & 31) + 220;

    for (int h = 0; h < 4; h++) {
        // S = Q K^T  (rows 16g..+15, all 128 cols, K=32)
        float sacc[8][2][4];
        #pragma unroll
        for (int np = 0; np < 8; np++)
            #pragma unroll
            for (int s2 = 0; s2 < 2; s2++)
                #pragma unroll
                for (int c = 0; c < 4; c++) sacc[np][s2][c] = 0.f;
        const uint32_t a0 = sb + SM_QS + (16 * g + ar) * PITCH + 64 * h + ak;
        const uint32_t b0 = sb + SM_KS + br * PITCH + 64 * h + bk;
        #pragma unroll
        for (int ks = 0; ks < 2; ks++) {
            uint32_t af[4];
            ldmx4(af, a0 + ks * 32);
            #pragma unroll
            for (int np = 0; np < 8; np++) {
                uint32_t bf[4];
                ldmx4(bf, b0 + np * 16 * PITCH + ks * 32);
                mma16816(sacc[np][0], af, &bf[0]);
                mma16816(sacc[np][1], af, &bf[2]);
            }
        }

        // softmax (no max-subtraction) + store P bf16
        const float* bh = bsm + h * 448;
        float rs0 = 0.f, rs1 = 0.f;
        __syncwarp();
        #pragma unroll
        for (int np = 0; np < 8; np++) {
            #pragma unroll
            for (int s2 = 0; s2 < 2; s2++) {
                int col = np * 16 + s2 * 8 + (lane & 3) * 2;
                int jh = col >> 5, jw = col & 31;
                int cgrp0 = ((wh < 15) ? 0 : ((jh < 2) ? 1 : 2)) * 3
                          + ((ww < 15) ? 0 : ((jw < 30) ? 1 : 2));
                int cgrp1 = ((wh < 15) ? 0 : ((jh < 2) ? 1 : 2)) * 3
                          + ((ww < 15) ? 0 : ((jw + 1 < 30) ? 1 : 2));
                int jo = jh * 63 + jw;
                float bb0 = bh[ib0 - jo], bb1 = bh[ib0 - jo - 1];
                float cb0 = bh[ib1 - jo], cb1 = bh[ib1 - jo - 1];
                float p00 = __expf(sacc[np][s2][0] + bb0 + ((cgrp0 != rgrp0) ? -100.f : 0.f));
                float p01 = __expf(sacc[np][s2][1] + bb1 + ((cgrp1 != rgrp0) ? -100.f : 0.f));
                float p10 = __expf(sacc[np][s2][2] + cb0 + ((cgrp0 != rgrp1) ? -100.f : 0.f));
                float p11 = __expf(sacc[np][s2][3] + cb1 + ((cgrp1 != rgrp1) ? -100.f : 0.f));
                rs0 += p00 + p01;
                rs1 += p10 + p11;
                *(__nv_bfloat162*)(smc + SM_XP + row0 * PITCH + col * 2) = __floats2bfloat162_rn(p00, p01);
                *(__nv_bfloat162*)(smc + SM_XP + row1 * PITCH + col * 2) = __floats2bfloat162_rn(p10, p11);
            }
        }
        rs0 += __shfl_xor_sync(0xFFFFFFFFu, rs0, 1);
        rs0 += __shfl_xor_sync(0xFFFFFFFFu, rs0, 2);
        rs1 += __shfl_xor_sync(0xFFFFFFFFu, rs1, 1);
        rs1 += __shfl_xor_sync(0xFFFFFFFFu, rs1, 2);
        float inv0 = 1.f / rs0, inv1 = 1.f / rs1;
        __syncwarp();

        // O = P V   (rows 16g..+15 x 32 dims, K=128)
        float oacc[4][4];
        #pragma unroll
        for (int j = 0; j < 4; j++)
            #pragma unroll
            for (int c = 0; c < 4; c++) oacc[j][c] = 0.f;
        const uint32_t pa = sb + SM_XP + (16 * g + ar) * PITCH + ak;
        const uint32_t vb = sb + SM_VT + (32 * h + br) * PITCH + bk;
        #pragma unroll
        for (int ks = 0; ks < 8; ks++) {
            uint32_t af[4];
            ldmx4(af, pa + ks * 32);
            #pragma unroll
            for (int np = 0; np < 2; np++) {
                uint32_t bf[4];
                ldmx4(bf, vb + np * 16 * PITCH + ks * 32);
                mma16816(oacc[np * 2 + 0], af, &bf[0]);
                mma16816(oacc[np * 2 + 1], af, &bf[2]);
            }
        }
        #pragma unroll
        for (int j = 0; j < 4; j++) {
            int col = 32 * h + j * 8 + (lane & 3) * 2;
            *(__nv_bfloat162*)(smc + SM_OS + row0 * PITCH + col * 2) =
                __floats2bfloat162_rn(oacc[j][0] * inv0, oacc[j][1] * inv0);
            *(__nv_bfloat162*)(smc + SM_OS + row1 * PITCH + col * 2) =
                __floats2bfloat162_rn(oacc[j][2] * inv1, oacc[j][3] * inv1);
        }
        __syncwarp();
    }

    // --- proj + window reverse + residual ---
    for (int i = t; i < 2048; i += 256) {
        int n = i >> 4, c16 = i & 15;
        uint4 u = *(const uint4*)(g_wp + (size_t)n * 128 + c16 * 8);
        *(uint4*)(smc + SM_WB + n * PITCH + c16 * 16) = u;
    }
    __syncthreads();
    float acc[4][4][4];
    ZERO_ACC(acc);
    warp_mma_tile_p(sb + SM_OS, PITCH, sb + SM_WB, acc, warp_m, warp_n, lane);

    #pragma unroll
    for (int mt = 0; mt < 4; mt++) {
        #pragma unroll
        for (int half = 0; half < 2; half++) {
            int row = warp_m * 64 + mt * 16 + (lane >> 2) + half * 8;
            int r = (wh * 4 + (row >> 5) + SHIFT) & 63;
            int c = (ww * 32 + (row & 31) + SHIFT) & 511;
            size_t base = ((size_t)(b * 64 + r) * 512 + c) * 128;
            #pragma unroll
            for (int j = 0; j < 4; j++) {
                int n = warp_n * 32 + j * 8 + (lane & 3) * 2;
                float2 xr = *(const float2*)(x + base + n);
                float2 v;
                v.x = xr.x + acc[mt][j][half * 2 + 0] + proj_b[n];
                v.y = xr.y + acc[mt][j][half * 2 + 1] + proj_b[n + 1];
                *(float2*)(g_x1 + base + n) = v;
            }
        }
    }
}

// smem offsets for k_mlp
#define SM_MX 0
#define SM_MW 34816
#define SM_MH 69632       // 128 x 1040 bytes (512 bf16 + pad)
#define HPITCH 1040
#define SM_MLP 202752

// ============== kernel 2: fused MLP (LN2 + fc1 + GELU + fc2 + residual) ==============
__global__ __launch_bounds__(256) void k_mlp(const float* __restrict__ g2,
                                             const float* __restrict__ b2,
                                             const float* __restrict__ fc1_b,
                                             const float* __restrict__ fc2_b,
                                             float* __restrict__ out) {
    extern __shared__ char smc[];
    const uint32_t sb = smem_u32(smc);
    const int tile = blockIdx.x;
    const int t = threadIdx.x, lane = t & 31, wid = t >> 5;
    const int warp_m = wid >> 2, warp_n = wid & 3;

    for (int i = t; i < 4096; i += 256) {
        int m = i >> 5, k4 = i & 31;
        float4 v = *(const float4*)(g_x1 + ((size_t)tile * 128 + m) * 128 + k4 * 4);
        __nv_bfloat162* d = (__nv_bfloat162*)(smc + SM_MX + m * PITCH + k4 * 8);
        d[0] = __floats2bfloat162_rn(v.x, v.y);
        d[1] = __floats2bfloat162_rn(v.z, v.w);
    }
    __syncthreads();
    if (t < 128) {
        __nv_bfloat16* row = (__nv_bfloat16*)(smc + SM_MX + t * PITCH);
        float s = 0.f, ss = 0.f;
        #pragma unroll 8
        for (int k = 0; k < 128; k++) { float v = __bfloat162float(row[k]); s += v; ss += v * v; }
        float mean = s * (1.f / 128.f);
        float rstd = rsqrtf(ss * (1.f / 128.f) - mean * mean + 1e-5f);
        #pragma unroll 4
        for (int k = 0; k < 128; k += 2) {
            float v0 = (__bfloat162float(row[k]) - mean) * rstd * g2[k] + b2[k];
            float v1 = (__bfloat162float(row[k + 1]) - mean) * rstd * g2[k + 1] + b2[k + 1];
            *(__nv_bfloat162*)(row + k) = __floats2bfloat162_rn(v0, v1);
        }
    }
    __syncthreads();

    // fc1 + GELU -> Hs (bf16, [m][512], pitch 1040B)
    for (int ct = 0; ct < 4; ct++) {
        for (int i = t; i < 2048; i += 256) {
            int n = i >> 4, c16 = i & 15;
            uint4 u = *(const uint4*)(g_w1 + (size_t)(ct * 128 + n) * 128 + c16 * 8);
            *(uint4*)(smc + SM_MW + n * PITCH + c16 * 16) = u;
        }
        __syncthreads();
        float acc[4][4][4];
        ZERO_ACC(acc);
        warp_mma_tile_p(sb + SM_MX, PITCH, sb + SM_MW, acc, warp_m, warp_n, lane);
        #pragma unroll
        for (int mt = 0; mt < 4; mt++) {
            #pragma unroll
            for (int half = 0; half < 2; half++) {
                int row = warp_m * 64 + mt * 16 + (lane >> 2) + half * 8;
                #pragma unroll
                for (int j = 0; j < 4; j++) {
                    int n = warp_n * 32 + j * 8 + (lane & 3) * 2;
                    float v0 = acc[mt][j][half * 2 + 0] + fc1_b[ct * 128 + n];
                    float v1 = acc[mt][j][half * 2 + 1] + fc1_b[ct * 128 + n + 1];
                    float e0 = 0.5f * v0 * (1.f + erff(v0 * 0.70710678118654752f));
                    float e1 = 0.5f * v1 * (1.f + erff(v1 * 0.70710678118654752f));
                    *(__nv_bfloat162*)(smc + SM_MH + row * HPITCH + (ct * 128 + n) * 2) =
                        __floats2bfloat162_rn(e0, e1);
                }
            }
        }
        __syncthreads();
    }

    // fc2 (K=512, 4 chunks) + residual
    float acc[4][4][4];
    ZERO_ACC(acc);
    for (int kc = 0; kc < 4; kc++) {
        for (int i = t; i < 2048; i += 256) {
            int n = i >> 4, c16 = i & 15;
            uint4 u = *(const uint4*)(g_w2 + (size_t)n * 512 + kc * 128 + c16 * 8);
            *(uint4*)(smc + SM_MW + n * PITCH + c16 * 16) = u;
        }
        __syncthreads();
        warp_mma_tile_p(sb + SM_MH + kc * 256, HPITCH, sb + SM_MW, acc, warp_m, warp_n, lane);
        __syncthreads();
    }
    #pragma unroll
    for (int mt = 0; mt < 4; mt++) {
        #pragma unroll
        for (int half = 0; half < 2; half++) {
            int row = warp_m * 64 + mt * 16 + (lane >> 2) + half * 8;
            const float* xr = g_x1 + ((size_t)tile * 128 + row) * 128;
            float* orow = out + ((size_t)tile * 128 + row) * 128;
            #pragma unroll
            for (int j = 0; j < 4; j++) {
                int n = warp_n * 32 + j * 8 + (lane & 3) * 2;
                float2 rv = *(const float2*)(xr + n);
                float2 v;
                v.x = rv.x + acc[mt][j][half * 2 + 0] + fc2_b[n];
                v.y = rv.y + acc[mt][j][half * 2 + 1] + fc2_b[n + 1];
                *(float2*)(orow + n) = v;
            }
        }
    }
}

// ---------------- launcher ----------------
extern "C" void kernel_launch(void* const* d_in, const int* in_sizes, int n_in,
                              void* d_out, int out_size) {
    (void)in_sizes; (void)n_in; (void)out_size;
    const float* x      = (const float*)d_in[0];
    const float* g1     = (const float*)d_in[1];
    const float* b1     = (const float*)d_in[2];
    const float* qkv_w  = (const float*)d_in[3];
    const float* qkv_b  = (const float*)d_in[4];
    const float* rpb    = (const float*)d_in[5];
    const float* proj_w = (const float*)d_in[6];
    const float* proj_b = (const float*)d_in[7];
    const float* g2     = (const float*)d_in[8];
    const float* b2     = (const float*)d_in[9];
    const float* fc1_w  = (const float*)d_in[10];
    const float* fc1_b  = (const float*)d_in[11];
    const float* fc2_w  = (const float*)d_in[12];
    const float* fc2_b  = (const float*)d_in[13];
    float* out = (float*)d_out;

    cudaFuncSetAttribute(k_wmsa, cudaFuncAttributeMaxDynamicSharedMemorySize, SM_WMSA);
    cudaFuncSetAttribute(k_mlp,  cudaFuncAttributeMaxDynamicSharedMemorySize, SM_MLP);

    k_prep<<<256, 256>>>(qkv_w, proj_w, fc1_w, fc2_w);
    k_wmsa<<<NWTOT, 256, SM_WMSA>>>(x, g1, b1, qkv_b, rpb, proj_b);
    k_mlp<<<TOK / 128, 256, SM_MLP>>>(g2, b2, fc1_b, fc2_b, out);
}

// round 5
// speedup vs baseline: 12.7579x; 1.4700x over previous
#include <cuda_runtime.h>
#include <cuda_bf16.h>
#include <math.h>
#include <stdint.h>

// ---------------- static config ----------------
#define NWTOT 2048
#define TOK   262144
#define SHIFT 2
#define SCALE 0.17677669529663687f
#define PITCH 272          // smem row pitch bytes (136 bf16), ldmatrix conflict-free

// ---------------- scratch ----------------
__device__ float g_x1[(size_t)TOK*128];
__device__ __nv_bfloat16 g_wq[384*128];   // qkv_w [n][k]
__device__ __nv_bfloat16 g_wp[128*128];   // proj_w [n][k]
__device__ __nv_bfloat16 g_w1[512*128];   // fc1_w [n][k]
__device__ __nv_bfloat16 g_w2[128*512];   // fc2_w [n][k]

// ---------------- helpers ----------------
__device__ __forceinline__ uint32_t smem_u32(const void* p) {
    uint32_t a;
    asm("{ .reg .u64 t; cvta.to.shared.u64 t, %1; cvt.u32.u64 %0, t; }" : "=r"(a) : "l"(p));
    return a;
}
__device__ __forceinline__ void ldmx4(uint32_t* r, uint32_t addr) {
    asm volatile("ldmatrix.sync.aligned.m8n8.x4.shared.b16 {%0,%1,%2,%3}, [%4];"
        : "=r"(r[0]), "=r"(r[1]), "=r"(r[2]), "=r"(r[3]) : "r"(addr));
}
__device__ __forceinline__ void ldmx4t(uint32_t* r, uint32_t addr) {
    asm volatile("ldmatrix.sync.aligned.m8n8.x4.trans.shared.b16 {%0,%1,%2,%3}, [%4];"
        : "=r"(r[0]), "=r"(r[1]), "=r"(r[2]), "=r"(r[3]) : "r"(addr));
}
__device__ __forceinline__ void mma16816(float* c, const uint32_t* a, const uint32_t* b) {
    asm volatile("mma.sync.aligned.m16n8k16.row.col.f32.bf16.bf16.f32 "
        "{%0,%1,%2,%3}, {%4,%5,%6,%7}, {%8,%9}, {%0,%1,%2,%3};"
        : "+f"(c[0]), "+f"(c[1]), "+f"(c[2]), "+f"(c[3])
        : "r"(a[0]), "r"(a[1]), "r"(a[2]), "r"(a[3]), "r"(b[0]), "r"(b[1]));
}
#define CP16(sm, gp)  asm volatile("cp.async.cg.shared.global [%0], [%1], 16;" :: "r"(sm), "l"(gp))
#define CP_COMMIT()   asm volatile("cp.async.commit_group;" ::: "memory")
#define CP_WAIT(n)    asm volatile("cp.async.wait_group %0;" :: "n"(n) : "memory")

__device__ __forceinline__ uint32_t packbf(float a, float b) {
    __nv_bfloat162 h = __floats2bfloat162_rn(a, b);
    return *(uint32_t*)&h;
}

// warp computes 32x32 of C over K=128. A: [m][k] pitch apitch; B: [n][k] pitch bpitch.
__device__ __forceinline__ void warp_mma32(uint32_t As, int apitch, uint32_t Bs, int bpitch,
                                           float acc[2][4][4], int wm, int wn, int lane) {
    const int ar = (lane & 7) + ((lane >> 3) & 1) * 8;
    const int ak = ((lane >> 4) & 1) * 16;
    const int br = (lane & 7) + ((lane >> 4) & 1) * 8;
    const int bk = ((lane >> 3) & 1) * 16;
    const uint32_t a_base = As + (wm * 32 + ar) * apitch + ak;
    const uint32_t b_base = Bs + (wn * 32 + br) * bpitch + bk;
    #pragma unroll
    for (int ks = 0; ks < 8; ks++) {
        uint32_t af[2][4], bf[2][4];
        #pragma unroll
        for (int mt = 0; mt < 2; mt++) ldmx4(af[mt], a_base + mt * 16 * apitch + ks * 32);
        #pragma unroll
        for (int np = 0; np < 2; np++) ldmx4(bf[np], b_base + np * 16 * bpitch + ks * 32);
        #pragma unroll
        for (int mt = 0; mt < 2; mt++) {
            mma16816(acc[mt][0], af[mt], &bf[0][0]);
            mma16816(acc[mt][1], af[mt], &bf[0][2]);
            mma16816(acc[mt][2], af[mt], &bf[1][0]);
            mma16816(acc[mt][3], af[mt], &bf[1][2]);
        }
    }
}
#define ZERO32(acc) do { \
    _Pragma("unroll") for (int _i = 0; _i < 2; _i++) \
    _Pragma("unroll") for (int _j = 0; _j < 4; _j++) \
    _Pragma("unroll") for (int _k = 0; _k < 4; _k++) acc[_i][_j][_k] = 0.f; } while (0)

// ============== kernel 0: weight pre-conversion ==============
__global__ __launch_bounds__(256) void k_prep(const float* __restrict__ qkv_w,
                                              const float* __restrict__ proj_w,
                                              const float* __restrict__ fc1_w,
                                              const float* __restrict__ fc2_w) {
    int e = blockIdx.x * 256 + threadIdx.x;
    if (e < 49152) { int n = e >> 7, k = e & 127; g_wq[e] = __float2bfloat16(qkv_w[(size_t)k * 384 + n]); }
    if (e < 16384) { int n = e >> 7, k = e & 127; g_wp[e] = __float2bfloat16(proj_w[(size_t)k * 128 + n]); }
    if (e < 65536) {
        { int n = e >> 7, k = e & 127; g_w1[e] = __float2bfloat16(fc1_w[(size_t)k * 512 + n]); }
        { int n = e >> 9, k = e & 511; g_w2[e] = __float2bfloat16(fc2_w[(size_t)k * 128 + n]); }
    }
}

// k_wmsa smem offsets (bytes)
#define SM_XS 0         // LN'd X; later proj weights
#define SM_QS 34816
#define SM_KS 69632
#define SM_VS 104448
#define SM_OS 139264    // QKV weight buf1 during QKV; O during attention
#define SM_WB 174080    // QKV weight buf0
#define SM_BI 208896    // rel-pos bias float[4][448]
#define SM_WMSA 216064

// ============== kernel 1: fused W-MSA ==============
__global__ __launch_bounds__(512) void k_wmsa(const float* __restrict__ x,
                                              const float* __restrict__ g1,
                                              const float* __restrict__ b1,
                                              const float* __restrict__ qkv_b,
                                              const float* __restrict__ rpb,
                                              const float* __restrict__ proj_b) {
    extern __shared__ char smc[];
    const uint32_t sb = smem_u32(smc);
    const int win = blockIdx.x;
    const int b = win >> 8, wi = win & 255, wh = wi >> 4, ww = wi & 15;
    const int t = threadIdx.x, lane = t & 31, wid = t >> 5;
    float* bsm = (float*)(smc + SM_BI);

    for (int i = t; i < 1764; i += 512) bsm[(i & 3) * 448 + (i >> 2)] = rpb[i];

    // --- LN1: warp-per-row, straight from global (shifted window) ---
    {
        const int k4 = lane * 4;
        const float4 gv = *(const float4*)(g1 + k4);
        const float4 bv = *(const float4*)(b1 + k4);
        #pragma unroll
        for (int r8 = 0; r8 < 8; r8++) {
            int m = wid * 8 + r8;
            int r = (wh * 4 + (m >> 5) + SHIFT) & 63;
            int c = (ww * 32 + (m & 31) + SHIFT) & 511;
            float4 xv = *(const float4*)(x + ((size_t)(b * 64 + r) * 512 + c) * 128 + k4);
            float s = xv.x + xv.y + xv.z + xv.w;
            float ss = xv.x * xv.x + xv.y * xv.y + xv.z * xv.z + xv.w * xv.w;
            #pragma unroll
            for (int o = 16; o > 0; o >>= 1) {
                s += __shfl_xor_sync(0xFFFFFFFFu, s, o);
                ss += __shfl_xor_sync(0xFFFFFFFFu, ss, o);
            }
            float mean = s * (1.f / 128.f);
            float rstd = rsqrtf(ss * (1.f / 128.f) - mean * mean + 1e-5f);
            uint2 u;
            u.x = packbf((xv.x - mean) * rstd * gv.x + bv.x, (xv.y - mean) * rstd * gv.y + bv.y);
            u.y = packbf((xv.z - mean) * rstd * gv.z + bv.z, (xv.w - mean) * rstd * gv.w + bv.w);
            *(uint2*)(smc + SM_XS + m * PITCH + k4 * 2) = u;
        }
    }
    // prefetch QKV weight chunk0
    for (int i = t; i < 2048; i += 512) {
        int n = i >> 4, c16 = i & 15;
        CP16(sb + SM_WB + n * PITCH + c16 * 16, g_wq + (size_t)n * 128 + c16 * 8);
    }
    CP_COMMIT();
    __syncthreads();

    // --- QKV GEMMs, double-buffered weights ---
    const int wm = wid >> 2, wn = wid & 3;
    const uint32_t wbuf[2] = { sb + SM_WB, sb + SM_OS };
    const int wboff[2] = { SM_WB, SM_OS }; (void)wboff;
    for (int ct = 0; ct < 3; ct++) {
        if (ct < 2) {
            uint32_t dst = wbuf[(ct + 1) & 1];
            for (int i = t; i < 2048; i += 512) {
                int n = i >> 4, c16 = i & 15;
                CP16(dst + n * PITCH + c16 * 16, g_wq + (size_t)((ct + 1) * 128 + n) * 128 + c16 * 8);
            }
            CP_COMMIT();
            CP_WAIT(1);
        } else {
            CP_WAIT(0);
        }
        __syncthreads();
        float acc[2][4][4];
        ZERO32(acc);
        warp_mma32(sb + SM_XS, PITCH, wbuf[ct & 1], PITCH, acc, wm, wn, lane);

        const int dsto = (ct == 0) ? SM_QS : ((ct == 1) ? SM_KS : SM_VS);
        const float scl = (ct == 0) ? SCALE : 1.f;
        #pragma unroll
        for (int mt = 0; mt < 2; mt++) {
            #pragma unroll
            for (int half = 0; half < 2; half++) {
                int row = wm * 32 + mt * 16 + (lane >> 2) + half * 8;
                #pragma unroll
                for (int j = 0; j < 4; j++) {
                    int col = wn * 32 + j * 8 + (lane & 3) * 2;
                    float bb0 = qkv_b[ct * 128 + col], bb1 = qkv_b[ct * 128 + col + 1];
                    *(uint32_t*)(smc + dsto + row * PITCH + col * 2) =
                        packbf((acc[mt][j][half * 2 + 0] + bb0) * scl,
                               (acc[mt][j][half * 2 + 1] + bb1) * scl);
                }
            }
        }
        __syncthreads();
    }

    // prefetch proj weights into XS (X is dead now)
    for (int i = t; i < 2048; i += 512) {
        int n = i >> 4, c16 = i & 15;
        CP16(sb + SM_XS + n * PITCH + c16 * 16, g_wp + (size_t)n * 128 + c16 * 8);
    }
    CP_COMMIT();

    // --- attention: 32 tasks (8 row-groups x 4 heads), 2 per warp ---
    const int ar = (lane & 7) + ((lane >> 3) & 1) * 8;
    const int ak = ((lane >> 4) & 1) * 16;
    const int br = (lane & 7) + ((lane >> 4) & 1) * 8;
    const int bk = ((lane >> 3) & 1) * 16;

    #pragma unroll
    for (int it = 0; it < 2; it++) {
        const int task = wid + it * 16;
        const int h = task >> 3, g = task & 7;
        const int row0 = 16 * g + (lane >> 2), row1 = row0 + 8;
        const int rgrp0 = ((wh < 15) ? 0 : (((row0 >> 5) < 2) ? 1 : 2)) * 3
                        + ((ww < 15) ? 0 : (((row0 & 31) < 30) ? 1 : 2));
        const int rgrp1 = ((wh < 15) ? 0 : (((row1 >> 5) < 2) ? 1 : 2)) * 3
                        + ((ww < 15) ? 0 : (((row1 & 31) < 30) ? 1 : 2));
        const int ib0 = (row0 >> 5) * 63 + (row0 & 31) + 220;
        const int ib1 = (row1 >> 5) * 63 + (row1 & 31) + 220;

        // S = Q K^T
        float sacc[8][2][4];
        #pragma unroll
        for (int np = 0; np < 8; np++)
            #pragma unroll
            for (int s2 = 0; s2 < 2; s2++)
                #pragma unroll
                for (int c = 0; c < 4; c++) sacc[np][s2][c] = 0.f;
        {
            const uint32_t a0 = sb + SM_QS + (16 * g + ar) * PITCH + 64 * h + ak;
            const uint32_t b0 = sb + SM_KS + br * PITCH + 64 * h + bk;
            uint32_t af[2][4];
            ldmx4(af[0], a0);
            ldmx4(af[1], a0 + 32);
            #pragma unroll
            for (int np = 0; np < 8; np++) {
                uint32_t bf0[4], bf1[4];
                ldmx4(bf0, b0 + np * 16 * PITCH);
                ldmx4(bf1, b0 + np * 16 * PITCH + 32);
                mma16816(sacc[np][0], af[0], &bf0[0]);
                mma16816(sacc[np][1], af[0], &bf0[2]);
                mma16816(sacc[np][0], af[1], &bf1[0]);
                mma16816(sacc[np][1], af[1], &bf1[2]);
            }
        }

        // softmax (no max) -> P kept in registers as A-fragments
        const float* bh = bsm + h * 448;
        uint32_t ap[8][4];
        float rs0 = 0.f, rs1 = 0.f;
        #pragma unroll
        for (int np = 0; np < 8; np++) {
            #pragma unroll
            for (int s2 = 0; s2 < 2; s2++) {
                int col = np * 16 + s2 * 8 + (lane & 3) * 2;
                int jh = col >> 5, jw = col & 31;
                int cg0 = ((wh < 15) ? 0 : ((jh < 2) ? 1 : 2)) * 3
                        + ((ww < 15) ? 0 : ((jw < 30) ? 1 : 2));
                int cg1 = ((wh < 15) ? 0 : ((jh < 2) ? 1 : 2)) * 3
                        + ((ww < 15) ? 0 : ((jw + 1 < 30) ? 1 : 2));
                int jo = jh * 63 + jw;
                float bb0 = bh[ib0 - jo], bb1 = bh[ib0 - jo - 1];
                float cb0 = bh[ib1 - jo], cb1 = bh[ib1 - jo - 1];
                float p00 = __expf(sacc[np][s2][0] + bb0 + ((cg0 != rgrp0) ? -100.f : 0.f));
                float p01 = __expf(sacc[np][s2][1] + bb1 + ((cg1 != rgrp0) ? -100.f : 0.f));
                float p10 = __expf(sacc[np][s2][2] + cb0 + ((cg0 != rgrp1) ? -100.f : 0.f));
                float p11 = __expf(sacc[np][s2][3] + cb1 + ((cg1 != rgrp1) ? -100.f : 0.f));
                rs0 += p00 + p01;
                rs1 += p10 + p11;
                ap[np][s2 * 2 + 0] = packbf(p00, p01);
                ap[np][s2 * 2 + 1] = packbf(p10, p11);
            }
        }
        rs0 += __shfl_xor_sync(0xFFFFFFFFu, rs0, 1);
        rs0 += __shfl_xor_sync(0xFFFFFFFFu, rs0, 2);
        rs1 += __shfl_xor_sync(0xFFFFFFFFu, rs1, 1);
        rs1 += __shfl_xor_sync(0xFFFFFFFFu, rs1, 2);
        const float inv0 = 1.f / rs0, inv1 = 1.f / rs1;

        // O = P V  (V as B-operand via ldmatrix.trans on [token][dim])
        float oacc[4][4];
        #pragma unroll
        for (int j = 0; j < 4; j++)
            #pragma unroll
            for (int c = 0; c < 4; c++) oacc[j][c] = 0.f;
        #pragma unroll
        for (int ks = 0; ks < 8; ks++) {
            uint32_t va = sb + SM_VS + (16 * ks + (lane & 15)) * PITCH + 64 * h
                        + ((lane >> 4) & 1) * 16;
            uint32_t bv0[4], bv1[4];
            ldmx4t(bv0, va);
            ldmx4t(bv1, va + 32);
            mma16816(oacc[0], ap[ks], &bv0[0]);
            mma16816(oacc[1], ap[ks], &bv0[2]);
            mma16816(oacc[2], ap[ks], &bv1[0]);
            mma16816(oacc[3], ap[ks], &bv1[2]);
        }
        #pragma unroll
        for (int j = 0; j < 4; j++) {
            int col = 32 * h + j * 8 + (lane & 3) * 2;
            *(uint32_t*)(smc + SM_OS + row0 * PITCH + col * 2) =
                packbf(oacc[j][0] * inv0, oacc[j][1] * inv0);
            *(uint32_t*)(smc + SM_OS + row1 * PITCH + col * 2) =
                packbf(oacc[j][2] * inv1, oacc[j][3] * inv1);
        }
    }
    CP_WAIT(0);
    __syncthreads();

    // --- proj + window reverse + residual ---
    float acc[2][4][4];
    ZERO32(acc);
    warp_mma32(sb + SM_OS, PITCH, sb + SM_XS, PITCH, acc, wm, wn, lane);
    #pragma unroll
    for (int mt = 0; mt < 2; mt++) {
        #pragma unroll
        for (int half = 0; half < 2; half++) {
            int row = wm * 32 + mt * 16 + (lane >> 2) + half * 8;
            int r = (wh * 4 + (row >> 5) + SHIFT) & 63;
            int c = (ww * 32 + (row & 31) + SHIFT) & 511;
            size_t base = ((size_t)(b * 64 + r) * 512 + c) * 128;
            #pragma unroll
            for (int j = 0; j < 4; j++) {
                int n = wn * 32 + j * 8 + (lane & 3) * 2;
                float2 xr = *(const float2*)(x + base + n);
                float2 v;
                v.x = xr.x + acc[mt][j][half * 2 + 0] + proj_b[n];
                v.y = xr.y + acc[mt][j][half * 2 + 1] + proj_b[n + 1];
                *(float2*)(g_x1 + base + n) = v;
            }
        }
    }
}

// k_mlp smem offsets
#define SM_MX 0
#define SM_MW 34816
#define SM_MH 69632
#define HPITCH 1040
#define SM_MLP 202752

// ============== kernel 2: fused MLP ==============
__global__ __launch_bounds__(512) void k_mlp(const float* __restrict__ g2,
                                             const float* __restrict__ b2,
                                             const float* __restrict__ fc1_b,
                                             const float* __restrict__ fc2_b,
                                             float* __restrict__ out) {
    extern __shared__ char smc[];
    const uint32_t sb = smem_u32(smc);
    const int tile = blockIdx.x;
    const int t = threadIdx.x, lane = t & 31, wid = t >> 5;
    const int wm = wid >> 2, wn = wid & 3;

    // LN2: warp-per-row
    {
        const int k4 = lane * 4;
        const float4 gv = *(const float4*)(g2 + k4);
        const float4 bv = *(const float4*)(b2 + k4);
        #pragma unroll
        for (int r8 = 0; r8 < 8; r8++) {
            int m = wid * 8 + r8;
            float4 xv = *(const float4*)(g_x1 + ((size_t)tile * 128 + m) * 128 + k4);
            float s = xv.x + xv.y + xv.z + xv.w;
            float ss = xv.x * xv.x + xv.y * xv.y + xv.z * xv.z + xv.w * xv.w;
            #pragma unroll
            for (int o = 16; o > 0; o >>= 1) {
                s += __shfl_xor_sync(0xFFFFFFFFu, s, o);
                ss += __shfl_xor_sync(0xFFFFFFFFu, ss, o);
            }
            float mean = s * (1.f / 128.f);
            float rstd = rsqrtf(ss * (1.f / 128.f) - mean * mean + 1e-5f);
            uint2 u;
            u.x = packbf((xv.x - mean) * rstd * gv.x + bv.x, (xv.y - mean) * rstd * gv.y + bv.y);
            u.y = packbf((xv.z - mean) * rstd * gv.z + bv.z, (xv.w - mean) * rstd * gv.w + bv.w);
            *(uint2*)(smc + SM_MX + m * PITCH + k4 * 2) = u;
        }
    }
    __syncthreads();

    // fc1 + GELU -> MH
    for (int ct = 0; ct < 4; ct++) {
        for (int i = t; i < 2048; i += 512) {
            int n = i >> 4, c16 = i & 15;
            *(uint4*)(smc + SM_MW + n * PITCH + c16 * 16) =
                *(const uint4*)(g_w1 + (size_t)(ct * 128 + n) * 128 + c16 * 8);
        }
        __syncthreads();
        float acc[2][4][4];
        ZERO32(acc);
        warp_mma32(sb + SM_MX, PITCH, sb + SM_MW, PITCH, acc, wm, wn, lane);
        #pragma unroll
        for (int mt = 0; mt < 2; mt++) {
            #pragma unroll
            for (int half = 0; half < 2; half++) {
                int row = wm * 32 + mt * 16 + (lane >> 2) + half * 8;
                #pragma unroll
                for (int j = 0; j < 4; j++) {
                    int n = wn * 32 + j * 8 + (lane & 3) * 2;
                    float v0 = acc[mt][j][half * 2 + 0] + fc1_b[ct * 128 + n];
                    float v1 = acc[mt][j][half * 2 + 1] + fc1_b[ct * 128 + n + 1];
                    float e0 = 0.5f * v0 * (1.f + erff(v0 * 0.70710678118654752f));
                    float e1 = 0.5f * v1 * (1.f + erff(v1 * 0.70710678118654752f));
                    *(uint32_t*)(smc + SM_MH + row * HPITCH + (ct * 128 + n) * 2) = packbf(e0, e1);
                }
            }
        }
        __syncthreads();
    }

    // fc2 (K=512 in 4 chunks) + residual
    float acc[2][4][4];
    ZERO32(acc);
    for (int kc = 0; kc < 4; kc++) {
        for (int i = t; i < 2048; i += 512) {
            int n = i >> 4, c16 = i & 15;
            *(uint4*)(smc + SM_MW + n * PITCH + c16 * 16) =
                *(const uint4*)(g_w2 + (size_t)n * 512 + kc * 128 + c16 * 8);
        }
        __syncthreads();
        warp_mma32(sb + SM_MH + kc * 256, HPITCH, sb + SM_MW, PITCH, acc, wm, wn, lane);
        __syncthreads();
    }
    #pragma unroll
    for (int mt = 0; mt < 2; mt++) {
        #pragma unroll
        for (int half = 0; half < 2; half++) {
            int row = wm * 32 + mt * 16 + (lane >> 2) + half * 8;
            const float* xr = g_x1 + ((size_t)tile * 128 + row) * 128;
            float* orow = out + ((size_t)tile * 128 + row) * 128;
            #pragma unroll
            for (int j = 0; j < 4; j++) {
                int n = wn * 32 + j * 8 + (lane & 3) * 2;
                float2 rv = *(const float2*)(xr + n);
                float2 v;
                v.x = rv.x + acc[mt][j][half * 2 + 0] + fc2_b[n];
                v.y = rv.y + acc[mt][j][half * 2 + 1] + fc2_b[n + 1];
                *(float2*)(orow + n) = v;
            }
        }
    }
}

// ---------------- launcher ----------------
extern "C" void kernel_launch(void* const* d_in, const int* in_sizes, int n_in,
                              void* d_out, int out_size) {
    (void)in_sizes; (void)n_in; (void)out_size;
    const float* x      = (const float*)d_in[0];
    const float* g1     = (const float*)d_in[1];
    const float* b1     = (const float*)d_in[2];
    const float* qkv_w  = (const float*)d_in[3];
    const float* qkv_b  = (const float*)d_in[4];
    const float* rpb    = (const float*)d_in[5];
    const float* proj_w = (const float*)d_in[6];
    const float* proj_b = (const float*)d_in[7];
    const float* g2     = (const float*)d_in[8];
    const float* b2     = (const float*)d_in[9];
    const float* fc1_w  = (const float*)d_in[10];
    const float* fc1_b  = (const float*)d_in[11];
    const float* fc2_w  = (const float*)d_in[12];
    const float* fc2_b  = (const float*)d_in[13];
    float* out = (float*)d_out;

    cudaFuncSetAttribute(k_wmsa, cudaFuncAttributeMaxDynamicSharedMemorySize, SM_WMSA);
    cudaFuncSetAttribute(k_mlp,  cudaFuncAttributeMaxDynamicSharedMemorySize, SM_MLP);

    k_prep<<<256, 256>>>(qkv_w, proj_w, fc1_w, fc2_w);
    k_wmsa<<<NWTOT, 512, SM_WMSA>>>(x, g1, b1, qkv_b, rpb, proj_b);
    k_mlp<<<TOK / 128, 512, SM_MLP>>>(g2, b2, fc1_b, fc2_b, out);
}

// round 6
// speedup vs baseline: 13.4487x; 1.0541x over previous
#include <cuda_runtime.h>
#include <cuda_bf16.h>
#include <math.h>
#include <stdint.h>

// ---------------- static config ----------------
#define NWTOT 2048
#define TOK   262144
#define SHIFT 2
#define SCALE 0.17677669529663687f
#define PITCH 272          // smem row pitch bytes (136 bf16), ldmatrix conflict-free

// ---------------- scratch ----------------
__device__ float g_x1[(size_t)TOK*128];
__device__ __nv_bfloat16 g_wq[384*128];   // qkv_w [n][k]
__device__ __nv_bfloat16 g_wp[128*128];   // proj_w [n][k]
__device__ __nv_bfloat16 g_w1[512*128];   // fc1_w [n][k]
__device__ __nv_bfloat16 g_w2[128*512];   // fc2_w [n][k]

// ---------------- helpers ----------------
__device__ __forceinline__ uint32_t smem_u32(const void* p) {
    uint32_t a;
    asm("{ .reg .u64 t; cvta.to.shared.u64 t, %1; cvt.u32.u64 %0, t; }" : "=r"(a) : "l"(p));
    return a;
}
__device__ __forceinline__ void ldmx4(uint32_t* r, uint32_t addr) {
    asm volatile("ldmatrix.sync.aligned.m8n8.x4.shared.b16 {%0,%1,%2,%3}, [%4];"
        : "=r"(r[0]), "=r"(r[1]), "=r"(r[2]), "=r"(r[3]) : "r"(addr));
}
__device__ __forceinline__ void ldmx4t(uint32_t* r, uint32_t addr) {
    asm volatile("ldmatrix.sync.aligned.m8n8.x4.trans.shared.b16 {%0,%1,%2,%3}, [%4];"
        : "=r"(r[0]), "=r"(r[1]), "=r"(r[2]), "=r"(r[3]) : "r"(addr));
}
__device__ __forceinline__ void mma16816(float* c, const uint32_t* a, const uint32_t* b) {
    asm volatile("mma.sync.aligned.m16n8k16.row.col.f32.bf16.bf16.f32 "
        "{%0,%1,%2,%3}, {%4,%5,%6,%7}, {%8,%9}, {%0,%1,%2,%3};"
        : "+f"(c[0]), "+f"(c[1]), "+f"(c[2]), "+f"(c[3])
        : "r"(a[0]), "r"(a[1]), "r"(a[2]), "r"(a[3]), "r"(b[0]), "r"(b[1]));
}
#define CP16(sm, gp)  asm volatile("cp.async.cg.shared.global [%0], [%1], 16;" :: "r"(sm), "l"(gp))
#define CP_COMMIT()   asm volatile("cp.async.commit_group;" ::: "memory")
#define CP_WAIT(n)    asm volatile("cp.async.wait_group %0;" :: "n"(n) : "memory")

__device__ __forceinline__ uint32_t packbf(float a, float b) {
    __nv_bfloat162 h = __floats2bfloat162_rn(a, b);
    return *(uint32_t*)&h;
}

// warp computes 32x32 of C over K=128. A: [m][k] pitch apitch; B: [n][k] pitch bpitch.
__device__ __forceinline__ void warp_mma32(uint32_t As, int apitch, uint32_t Bs, int bpitch,
                                           float acc[2][4][4], int wm, int wn, int lane) {
    const int ar = (lane & 7) + ((lane >> 3) & 1) * 8;
    const int ak = ((lane >> 4) & 1) * 16;
    const int br = (lane & 7) + ((lane >> 4) & 1) * 8;
    const int bk = ((lane >> 3) & 1) * 16;
    const uint32_t a_base = As + (wm * 32 + ar) * apitch + ak;
    const uint32_t b_base = Bs + (wn * 32 + br) * bpitch + bk;
    #pragma unroll
    for (int ks = 0; ks < 8; ks++) {
        uint32_t af[2][4], bf[2][4];
        #pragma unroll
        for (int mt = 0; mt < 2; mt++) ldmx4(af[mt], a_base + mt * 16 * apitch + ks * 32);
        #pragma unroll
        for (int np = 0; np < 2; np++) ldmx4(bf[np], b_base + np * 16 * bpitch + ks * 32);
        #pragma unroll
        for (int mt = 0; mt < 2; mt++) {
            mma16816(acc[mt][0], af[mt], &bf[0][0]);
            mma16816(acc[mt][1], af[mt], &bf[0][2]);
            mma16816(acc[mt][2], af[mt], &bf[1][0]);
            mma16816(acc[mt][3], af[mt], &bf[1][2]);
        }
    }
}
#define ZERO32(acc) do { \
    _Pragma("unroll") for (int _i = 0; _i < 2; _i++) \
    _Pragma("unroll") for (int _j = 0; _j < 4; _j++) \
    _Pragma("unroll") for (int _k = 0; _k < 4; _k++) acc[_i][_j][_k] = 0.f; } while (0)

// ============== kernel 0: weight pre-conversion ==============
__global__ __launch_bounds__(256) void k_prep(const float* __restrict__ qkv_w,
                                              const float* __restrict__ proj_w,
                                              const float* __restrict__ fc1_w,
                                              const float* __restrict__ fc2_w) {
    int e = blockIdx.x * 256 + threadIdx.x;
    if (e < 49152) { int n = e >> 7, k = e & 127; g_wq[e] = __float2bfloat16(qkv_w[(size_t)k * 384 + n]); }
    if (e < 16384) { int n = e >> 7, k = e & 127; g_wp[e] = __float2bfloat16(proj_w[(size_t)k * 128 + n]); }
    if (e < 65536) {
        { int n = e >> 7, k = e & 127; g_w1[e] = __float2bfloat16(fc1_w[(size_t)k * 512 + n]); }
        { int n = e >> 9, k = e & 511; g_w2[e] = __float2bfloat16(fc2_w[(size_t)k * 128 + n]); }
    }
}

// k_wmsa smem offsets (bytes)
#define SM_XS 0         // LN'd X; later proj weights
#define SM_QS 34816
#define SM_KS 69632
#define SM_VS 104448
#define SM_OS 139264    // QKV weight buf1 during QKV; O during attention
#define SM_WB 174080    // QKV weight buf0
#define SM_BI 208896    // rel-pos bias float[4][448]
#define SM_WMSA 216064

// ============== kernel 1: fused W-MSA ==============
__global__ __launch_bounds__(512) void k_wmsa(const float* __restrict__ x,
                                              const float* __restrict__ g1,
                                              const float* __restrict__ b1,
                                              const float* __restrict__ qkv_b,
                                              const float* __restrict__ rpb,
                                              const float* __restrict__ proj_b) {
    extern __shared__ char smc[];
    const uint32_t sb = smem_u32(smc);
    const int win = blockIdx.x;
    const int b = win >> 8, wi = win & 255, wh = wi >> 4, ww = wi & 15;
    const int t = threadIdx.x, lane = t & 31, wid = t >> 5;
    float* bsm = (float*)(smc + SM_BI);

    for (int i = t; i < 1764; i += 512) bsm[(i & 3) * 448 + (i >> 2)] = rpb[i];

    // --- LN1: warp-per-row ---
    {
        const int k4 = lane * 4;
        const float4 gv = *(const float4*)(g1 + k4);
        const float4 bv = *(const float4*)(b1 + k4);
        #pragma unroll
        for (int r8 = 0; r8 < 8; r8++) {
            int m = wid * 8 + r8;
            int r = (wh * 4 + (m >> 5) + SHIFT) & 63;
            int c = (ww * 32 + (m & 31) + SHIFT) & 511;
            float4 xv = *(const float4*)(x + ((size_t)(b * 64 + r) * 512 + c) * 128 + k4);
            float s = xv.x + xv.y + xv.z + xv.w;
            float ss = xv.x * xv.x + xv.y * xv.y + xv.z * xv.z + xv.w * xv.w;
            #pragma unroll
            for (int o = 16; o > 0; o >>= 1) {
                s += __shfl_xor_sync(0xFFFFFFFFu, s, o);
                ss += __shfl_xor_sync(0xFFFFFFFFu, ss, o);
            }
            float mean = s * (1.f / 128.f);
            float rstd = rsqrtf(ss * (1.f / 128.f) - mean * mean + 1e-5f);
            uint2 u;
            u.x = packbf((xv.x - mean) * rstd * gv.x + bv.x, (xv.y - mean) * rstd * gv.y + bv.y);
            u.y = packbf((xv.z - mean) * rstd * gv.z + bv.z, (xv.w - mean) * rstd * gv.w + bv.w);
            *(uint2*)(smc + SM_XS + m * PITCH + k4 * 2) = u;
        }
    }
    for (int i = t; i < 2048; i += 512) {
        int n = i >> 4, c16 = i & 15;
        CP16(sb + SM_WB + n * PITCH + c16 * 16, g_wq + (size_t)n * 128 + c16 * 8);
    }
    CP_COMMIT();
    __syncthreads();

    // --- QKV GEMMs, double-buffered weights ---
    const int wm = wid >> 2, wn = wid & 3;
    const uint32_t wbuf[2] = { sb + SM_WB, sb + SM_OS };
    for (int ct = 0; ct < 3; ct++) {
        if (ct < 2) {
            uint32_t dst = wbuf[(ct + 1) & 1];
            for (int i = t; i < 2048; i += 512) {
                int n = i >> 4, c16 = i & 15;
                CP16(dst + n * PITCH + c16 * 16, g_wq + (size_t)((ct + 1) * 128 + n) * 128 + c16 * 8);
            }
            CP_COMMIT();
            CP_WAIT(1);
        } else {
            CP_WAIT(0);
        }
        __syncthreads();
        float acc[2][4][4];
        ZERO32(acc);
        warp_mma32(sb + SM_XS, PITCH, wbuf[ct & 1], PITCH, acc, wm, wn, lane);

        const int dsto = (ct == 0) ? SM_QS : ((ct == 1) ? SM_KS : SM_VS);
        const float scl = (ct == 0) ? SCALE : 1.f;
        float bb[4][2];
        #pragma unroll
        for (int j = 0; j < 4; j++) {
            int col = wn * 32 + j * 8 + (lane & 3) * 2;
            bb[j][0] = qkv_b[ct * 128 + col];
            bb[j][1] = qkv_b[ct * 128 + col + 1];
        }
        #pragma unroll
        for (int mt = 0; mt < 2; mt++) {
            #pragma unroll
            for (int half = 0; half < 2; half++) {
                int row = wm * 32 + mt * 16 + (lane >> 2) + half * 8;
                #pragma unroll
                for (int j = 0; j < 4; j++) {
                    int col = wn * 32 + j * 8 + (lane & 3) * 2;
                    *(uint32_t*)(smc + dsto + row * PITCH + col * 2) =
                        packbf((acc[mt][j][half * 2 + 0] + bb[j][0]) * scl,
                               (acc[mt][j][half * 2 + 1] + bb[j][1]) * scl);
                }
            }
        }
        __syncthreads();
    }

    // prefetch proj weights into XS (X is dead now)
    for (int i = t; i < 2048; i += 512) {
        int n = i >> 4, c16 = i & 15;
        CP16(sb + SM_XS + n * PITCH + c16 * 16, g_wp + (size_t)n * 128 + c16 * 8);
    }
    CP_COMMIT();

    // --- attention ---
    const int ar = (lane & 7) + ((lane >> 3) & 1) * 8;
    const int ak = ((lane >> 4) & 1) * 16;
    const int br = (lane & 7) + ((lane >> 4) & 1) * 8;
    const int bk = ((lane >> 3) & 1) * 16;
    const bool edge = (wh == 15) || (ww == 15);

    #pragma unroll
    for (int it = 0; it < 2; it++) {
        const int task = wid + it * 16;
        const int h = task >> 3, g = task & 7;
        const int row0 = 16 * g + (lane >> 2), row1 = row0 + 8;
        const int ib0 = (row0 >> 5) * 63 + (row0 & 31) + 220;
        const int ib1 = (row1 >> 5) * 63 + (row1 & 31) + 220;

        // S = Q K^T
        float sacc[8][2][4];
        #pragma unroll
        for (int np = 0; np < 8; np++)
            #pragma unroll
            for (int s2 = 0; s2 < 2; s2++)
                #pragma unroll
                for (int c = 0; c < 4; c++) sacc[np][s2][c] = 0.f;
        {
            const uint32_t a0 = sb + SM_QS + (16 * g + ar) * PITCH + 64 * h + ak;
            const uint32_t b0 = sb + SM_KS + br * PITCH + 64 * h + bk;
            uint32_t af[2][4];
            ldmx4(af[0], a0);
            ldmx4(af[1], a0 + 32);
            #pragma unroll
            for (int np = 0; np < 8; np++) {
                uint32_t bf0[4], bf1[4];
                ldmx4(bf0, b0 + np * 16 * PITCH);
                ldmx4(bf1, b0 + np * 16 * PITCH + 32);
                mma16816(sacc[np][0], af[0], &bf0[0]);
                mma16816(sacc[np][1], af[0], &bf0[2]);
                mma16816(sacc[np][0], af[1], &bf1[0]);
                mma16816(sacc[np][1], af[1], &bf1[2]);
            }
        }

        // softmax (no max) -> P in registers as A-fragments
        const float* bh = bsm + h * 448;
        uint32_t ap[8][4];
        float rs0 = 0.f, rs1 = 0.f;
        if (!edge) {
            #pragma unroll
            for (int np = 0; np < 8; np++) {
                #pragma unroll
                for (int s2 = 0; s2 < 2; s2++) {
                    int col = np * 16 + s2 * 8 + (lane & 3) * 2;
                    int jo = (col >> 5) * 63 + (col & 31);
                    float p00 = __expf(sacc[np][s2][0] + bh[ib0 - jo]);
                    float p01 = __expf(sacc[np][s2][1] + bh[ib0 - jo - 1]);
                    float p10 = __expf(sacc[np][s2][2] + bh[ib1 - jo]);
                    float p11 = __expf(sacc[np][s2][3] + bh[ib1 - jo - 1]);
                    rs0 += p00 + p01;
                    rs1 += p10 + p11;
                    ap[np][s2 * 2 + 0] = packbf(p00, p01);
                    ap[np][s2 * 2 + 1] = packbf(p10, p11);
                }
            }
        } else {
            const int rgrp0 = ((wh < 15) ? 0 : (((row0 >> 5) < 2) ? 1 : 2)) * 3
                            + ((ww < 15) ? 0 : (((row0 & 31) < 30) ? 1 : 2));
            const int rgrp1 = ((wh < 15) ? 0 : (((row1 >> 5) < 2) ? 1 : 2)) * 3
                            + ((ww < 15) ? 0 : (((row1 & 31) < 30) ? 1 : 2));
            #pragma unroll
            for (int np = 0; np < 8; np++) {
                #pragma unroll
                for (int s2 = 0; s2 < 2; s2++) {
                    int col = np * 16 + s2 * 8 + (lane & 3) * 2;
                    int jh = col >> 5, jw = col & 31;
                    int cg0 = ((wh < 15) ? 0 : ((jh < 2) ? 1 : 2)) * 3
                            + ((ww < 15) ? 0 : ((jw < 30) ? 1 : 2));
                    int cg1 = ((wh < 15) ? 0 : ((jh < 2) ? 1 : 2)) * 3
                            + ((ww < 15) ? 0 : ((jw + 1 < 30) ? 1 : 2));
                    int jo = jh * 63 + jw;
                    float p00 = __expf(sacc[np][s2][0] + bh[ib0 - jo] + ((cg0 != rgrp0) ? -100.f : 0.f));
                    float p01 = __expf(sacc[np][s2][1] + bh[ib0 - jo - 1] + ((cg1 != rgrp0) ? -100.f : 0.f));
                    float p10 = __expf(sacc[np][s2][2] + bh[ib1 - jo] + ((cg0 != rgrp1) ? -100.f : 0.f));
                    float p11 = __expf(sacc[np][s2][3] + bh[ib1 - jo - 1] + ((cg1 != rgrp1) ? -100.f : 0.f));
                    rs0 += p00 + p01;
                    rs1 += p10 + p11;
                    ap[np][s2 * 2 + 0] = packbf(p00, p01);
                    ap[np][s2 * 2 + 1] = packbf(p10, p11);
                }
            }
        }
        rs0 += __shfl_xor_sync(0xFFFFFFFFu, rs0, 1);
        rs0 += __shfl_xor_sync(0xFFFFFFFFu, rs0, 2);
        rs1 += __shfl_xor_sync(0xFFFFFFFFu, rs1, 1);
        rs1 += __shfl_xor_sync(0xFFFFFFFFu, rs1, 2);
        const float inv0 = 1.f / rs0, inv1 = 1.f / rs1;

        // O = P V
        float oacc[4][4];
        #pragma unroll
        for (int j = 0; j < 4; j++)
            #pragma unroll
            for (int c = 0; c < 4; c++) oacc[j][c] = 0.f;
        #pragma unroll
        for (int ks = 0; ks < 8; ks++) {
            uint32_t va = sb + SM_VS + (16 * ks + (lane & 15)) * PITCH + 64 * h
                        + ((lane >> 4) & 1) * 16;
            uint32_t bv0[4], bv1[4];
            ldmx4t(bv0, va);
            ldmx4t(bv1, va + 32);
            mma16816(oacc[0], ap[ks], &bv0[0]);
            mma16816(oacc[1], ap[ks], &bv0[2]);
            mma16816(oacc[2], ap[ks], &bv1[0]);
            mma16816(oacc[3], ap[ks], &bv1[2]);
        }
        #pragma unroll
        for (int j = 0; j < 4; j++) {
            int col = 32 * h + j * 8 + (lane & 3) * 2;
            *(uint32_t*)(smc + SM_OS + row0 * PITCH + col * 2) =
                packbf(oacc[j][0] * inv0, oacc[j][1] * inv0);
            *(uint32_t*)(smc + SM_OS + row1 * PITCH + col * 2) =
                packbf(oacc[j][2] * inv1, oacc[j][3] * inv1);
        }
    }
    CP_WAIT(0);
    __syncthreads();

    // --- proj + window reverse + residual ---
    float acc[2][4][4];
    ZERO32(acc);
    warp_mma32(sb + SM_OS, PITCH, sb + SM_XS, PITCH, acc, wm, wn, lane);
    #pragma unroll
    for (int mt = 0; mt < 2; mt++) {
        #pragma unroll
        for (int half = 0; half < 2; half++) {
            int row = wm * 32 + mt * 16 + (lane >> 2) + half * 8;
            int r = (wh * 4 + (row >> 5) + SHIFT) & 63;
            int c = (ww * 32 + (row & 31) + SHIFT) & 511;
            size_t base = ((size_t)(b * 64 + r) * 512 + c) * 128;
            #pragma unroll
            for (int j = 0; j < 4; j++) {
                int n = wn * 32 + j * 8 + (lane & 3) * 2;
                float2 xr = *(const float2*)(x + base + n);
                float2 v;
                v.x = xr.x + acc[mt][j][half * 2 + 0] + proj_b[n];
                v.y = xr.y + acc[mt][j][half * 2 + 1] + proj_b[n + 1];
                *(float2*)(g_x1 + base + n) = v;
            }
        }
    }
}

// k_mlp smem: W0 | W1 | H (128 x 1024B, XOR swizzle; X aliased to H cols 384..511)
#define SM_W1O 34816
#define SM_H2  69632
#define SM_MLP2 200704

// ============== kernel 2: fused MLP (pipelined) ==============
__global__ __launch_bounds__(512) void k_mlp(const float* __restrict__ g2,
                                             const float* __restrict__ b2,
                                             const float* __restrict__ fc1_b,
                                             const float* __restrict__ fc2_b,
                                             float* __restrict__ out) {
    extern __shared__ char smc[];
    const uint32_t sb = smem_u32(smc);
    const uint32_t Wb[2] = { sb, sb + SM_W1O };
    const uint32_t Hs = sb + SM_H2;
    const int tile = blockIdx.x;
    const int t = threadIdx.x, lane = t & 31, wid = t >> 5;
    const int wm = wid >> 2, wn = wid & 3;

    // prefetch fc1 chunk 0
    for (int i = t; i < 2048; i += 512) {
        int n = i >> 4, c16 = i & 15;
        CP16(Wb[0] + n * PITCH + c16 * 16, g_w1 + (size_t)n * 128 + c16 * 8);
    }
    CP_COMMIT();

    // LN2 -> X (aliased to H byte cols 768..1023, XOR swizzle)
    {
        const int k4 = lane * 4;
        const float4 gv = *(const float4*)(g2 + k4);
        const float4 bv = *(const float4*)(b2 + k4);
        #pragma unroll
        for (int r8 = 0; r8 < 8; r8++) {
            int m = wid * 8 + r8;
            float4 xv = *(const float4*)(g_x1 + ((size_t)tile * 128 + m) * 128 + k4);
            float s = xv.x + xv.y + xv.z + xv.w;
            float ss = xv.x * xv.x + xv.y * xv.y + xv.z * xv.z + xv.w * xv.w;
            #pragma unroll
            for (int o = 16; o > 0; o >>= 1) {
                s += __shfl_xor_sync(0xFFFFFFFFu, s, o);
                ss += __shfl_xor_sync(0xFFFFFFFFu, ss, o);
            }
            float mean = s * (1.f / 128.f);
            float rstd = rsqrtf(ss * (1.f / 128.f) - mean * mean + 1e-5f);
            uint2 u;
            u.x = packbf((xv.x - mean) * rstd * gv.x + bv.x, (xv.y - mean) * rstd * gv.y + bv.y);
            u.y = packbf((xv.z - mean) * rstd * gv.z + bv.z, (xv.w - mean) * rstd * gv.w + bv.w);
            *(uint2*)(smc + SM_H2 + m * 1024 + ((768 + lane * 8) ^ ((m & 7) << 4))) = u;
        }
    }
    __syncthreads();

    const int ar = (lane & 7) + ((lane >> 3) & 1) * 8;
    const int ak = ((lane >> 4) & 1) * 16;
    const int br = (lane & 7) + ((lane >> 4) & 1) * 8;
    const int bk = ((lane >> 3) & 1) * 16;

    // preload X A-fragments (reused across all 4 fc1 chunks)
    uint32_t xa[8][2][4];
    #pragma unroll
    for (int ks = 0; ks < 8; ks++)
        #pragma unroll
        for (int mt = 0; mt < 2; mt++) {
            int row = wm * 32 + mt * 16 + ar;
            ldmx4(xa[ks][mt], Hs + row * 1024
                  + (uint32_t)((768 + ak + ks * 32) ^ ((row & 7) << 4)));
        }

    // fc1: 4 chunks, pipelined
    for (int ct = 0; ct < 4; ct++) {
        CP_WAIT(0);
        __syncthreads();
        {
            int nc = ct + 1;                 // chunks 1..3 = fc1; 4 = fc2 kc0
            uint32_t dst = Wb[nc & 1];
            for (int i = t; i < 2048; i += 512) {
                int n = i >> 4, c16 = i & 15;
                const __nv_bfloat16* src = (nc < 4)
                    ? g_w1 + (size_t)(nc * 128 + n) * 128 + c16 * 8
                    : g_w2 + (size_t)n * 512 + c16 * 8;
                CP16(dst + n * PITCH + c16 * 16, src);
            }
            CP_COMMIT();
        }
        float acc[2][4][4];
        ZERO32(acc);
        const uint32_t b_base = Wb[ct & 1] + (wn * 32 + br) * PITCH + bk;
        #pragma unroll
        for (int ks = 0; ks < 8; ks++) {
            uint32_t bf[2][4];
            ldmx4(bf[0], b_base + ks * 32);
            ldmx4(bf[1], b_base + 16 * PITCH + ks * 32);
            #pragma unroll
            for (int mt = 0; mt < 2; mt++) {
                mma16816(acc[mt][0], xa[ks][mt], &bf[0][0]);
                mma16816(acc[mt][1], xa[ks][mt], &bf[0][2]);
                mma16816(acc[mt][2], xa[ks][mt], &bf[1][0]);
                mma16816(acc[mt][3], xa[ks][mt], &bf[1][2]);
            }
        }
        if (ct == 3) __syncthreads();        // X fully consumed before overwrite
        #pragma unroll
        for (int mt = 0; mt < 2; mt++) {
            #pragma unroll
            for (int half = 0; half < 2; half++) {
                int row = wm * 32 + mt * 16 + (lane >> 2) + half * 8;
                #pragma unroll
                for (int j = 0; j < 4; j++) {
                    int n = wn * 32 + j * 8 + (lane & 3) * 2;
                    float v0 = acc[mt][j][half * 2 + 0] + fc1_b[ct * 128 + n];
                    float v1 = acc[mt][j][half * 2 + 1] + fc1_b[ct * 128 + n + 1];
                    float e0 = 0.5f * v0 * (1.f + erff(v0 * 0.70710678118654752f));
                    float e1 = 0.5f * v1 * (1.f + erff(v1 * 0.70710678118654752f));
                    *(uint32_t*)(smc + SM_H2 + row * 1024
                        + (uint32_t)((((ct * 128 + n) * 2)) ^ ((row & 7) << 4))) = packbf(e0, e1);
                }
            }
        }
    }

    // fc2: 4 chunks (K=512), pipelined, accumulate
    float acc2[2][4][4];
    ZERO32(acc2);
    for (int kc = 0; kc < 4; kc++) {
        CP_WAIT(0);
        __syncthreads();
        if (kc < 3) {
            int nc = 5 + kc;                 // chunks 5..7 = fc2 kc 1..3
            uint32_t dst = Wb[nc & 1];
            for (int i = t; i < 2048; i += 512) {
                int n = i >> 4, c16 = i & 15;
                CP16(dst + n * PITCH + c16 * 16,
                     g_w2 + (size_t)n * 512 + (nc - 4) * 128 + c16 * 8);
            }
            CP_COMMIT();
        }
        const uint32_t b_base = Wb[kc & 1] + (wn * 32 + br) * PITCH + bk;
        #pragma unroll
        for (int ks = 0; ks < 8; ks++) {
            uint32_t af[2][4], bf[2][4];
            #pragma unroll
            for (int mt = 0; mt < 2; mt++) {
                int row = wm * 32 + mt * 16 + ar;
                ldmx4(af[mt], Hs + row * 1024
                      + (uint32_t)((kc * 256 + ak + ks * 32) ^ ((row & 7) << 4)));
            }
            ldmx4(bf[0], b_base + ks * 32);
            ldmx4(bf[1], b_base + 16 * PITCH + ks * 32);
            #pragma unroll
            for (int mt = 0; mt < 2; mt++) {
                mma16816(acc2[mt][0], af[mt], &bf[0][0]);
                mma16816(acc2[mt][1], af[mt], &bf[0][2]);
                mma16816(acc2[mt][2], af[mt], &bf[1][0]);
                mma16816(acc2[mt][3], af[mt], &bf[1][2]);
            }
        }
    }
    #pragma unroll
    for (int mt = 0; mt < 2; mt++) {
        #pragma unroll
        for (int half = 0; half < 2; half++) {
            int row = wm * 32 + mt * 16 + (lane >> 2) + half * 8;
            const float* xr = g_x1 + ((size_t)tile * 128 + row) * 128;
            float* orow = out + ((size_t)tile * 128 + row) * 128;
            #pragma unroll
            for (int j = 0; j < 4; j++) {
                int n = wn * 32 + j * 8 + (lane & 3) * 2;
                float2 rv = *(const float2*)(xr + n);
                float2 v;
                v.x = rv.x + acc2[mt][j][half * 2 + 0] + fc2_b[n];
                v.y = rv.y + acc2[mt][j][half * 2 + 1] + fc2_b[n + 1];
                *(float2*)(orow + n) = v;
            }
        }
    }
}

// ---------------- launcher ----------------
extern "C" void kernel_launch(void* const* d_in, const int* in_sizes, int n_in,
                              void* d_out, int out_size) {
    (void)in_sizes; (void)n_in; (void)out_size;
    const float* x      = (const float*)d_in[0];
    const float* g1     = (const float*)d_in[1];
    const float* b1     = (const float*)d_in[2];
    const float* qkv_w  = (const float*)d_in[3];
    const float* qkv_b  = (const float*)d_in[4];
    const float* rpb    = (const float*)d_in[5];
    const float* proj_w = (const float*)d_in[6];
    const float* proj_b = (const float*)d_in[7];
    const float* g2     = (const float*)d_in[8];
    const float* b2     = (const float*)d_in[9];
    const float* fc1_w  = (const float*)d_in[10];
    const float* fc1_b  = (const float*)d_in[11];
    const float* fc2_w  = (const float*)d_in[12];
    const float* fc2_b  = (const float*)d_in[13];
    float* out = (float*)d_out;

    cudaFuncSetAttribute(k_wmsa, cudaFuncAttributeMaxDynamicSharedMemorySize, SM_WMSA);
    cudaFuncSetAttribute(k_mlp,  cudaFuncAttributeMaxDynamicSharedMemorySize, SM_MLP2);

    k_prep<<<256, 256>>>(qkv_w, proj_w, fc1_w, fc2_w);
    k_wmsa<<<NWTOT, 512, SM_WMSA>>>(x, g1, b1, qkv_b, rpb, proj_b);
    k_mlp<<<TOK / 128, 512, SM_MLP2>>>(g2, b2, fc1_b, fc2_b, out);
}

// round 7
// speedup vs baseline: 14.8090x; 1.1012x over previous
#include <cuda_runtime.h>
#include <cuda_bf16.h>
#include <math.h>
#include <stdint.h>

// ---------------- static config ----------------
#define NWTOT 2048
#define TOK   262144
#define SHIFT 2
#define SCALE 0.17677669529663687f
#define PITCH 272          // smem row pitch bytes (136 bf16), ldmatrix conflict-free

// ---------------- scratch ----------------
__device__ float g_x1[(size_t)TOK*128];
__device__ __nv_bfloat16 g_wq[384*128];   // qkv_w [n][k]
__device__ __nv_bfloat16 g_wp[128*128];   // proj_w [n][k]
__device__ __nv_bfloat16 g_w1[512*128];   // fc1_w [n][k]
__device__ __nv_bfloat16 g_w2[128*512];   // fc2_w [n][k]

// ---------------- helpers ----------------
__device__ __forceinline__ uint32_t smem_u32(const void* p) {
    uint32_t a;
    asm("{ .reg .u64 t; cvta.to.shared.u64 t, %1; cvt.u32.u64 %0, t; }" : "=r"(a) : "l"(p));
    return a;
}
__device__ __forceinline__ void ldmx4(uint32_t* r, uint32_t addr) {
    asm volatile("ldmatrix.sync.aligned.m8n8.x4.shared.b16 {%0,%1,%2,%3}, [%4];"
        : "=r"(r[0]), "=r"(r[1]), "=r"(r[2]), "=r"(r[3]) : "r"(addr));
}
__device__ __forceinline__ void ldmx4t(uint32_t* r, uint32_t addr) {
    asm volatile("ldmatrix.sync.aligned.m8n8.x4.trans.shared.b16 {%0,%1,%2,%3}, [%4];"
        : "=r"(r[0]), "=r"(r[1]), "=r"(r[2]), "=r"(r[3]) : "r"(addr));
}
__device__ __forceinline__ void mma16816(float* c, const uint32_t* a, const uint32_t* b) {
    asm volatile("mma.sync.aligned.m16n8k16.row.col.f32.bf16.bf16.f32 "
        "{%0,%1,%2,%3}, {%4,%5,%6,%7}, {%8,%9}, {%0,%1,%2,%3};"
        : "+f"(c[0]), "+f"(c[1]), "+f"(c[2]), "+f"(c[3])
        : "r"(a[0]), "r"(a[1]), "r"(a[2]), "r"(a[3]), "r"(b[0]), "r"(b[1]));
}
#define CP16(sm, gp)  asm volatile("cp.async.cg.shared.global [%0], [%1], 16;" :: "r"(sm), "l"(gp))
#define CP_COMMIT()   asm volatile("cp.async.commit_group;" ::: "memory")
#define CP_WAIT(n)    asm volatile("cp.async.wait_group %0;" :: "n"(n) : "memory")

__device__ __forceinline__ uint32_t packbf(float a, float b) {
    __nv_bfloat162 h = __floats2bfloat162_rn(a, b);
    return *(uint32_t*)&h;
}

// warp computes 32x32 of C over K=128. A: [m][k] pitch apitch; B: [n][k] pitch bpitch.
__device__ __forceinline__ void warp_mma32(uint32_t As, int apitch, uint32_t Bs, int bpitch,
                                           float acc[2][4][4], int wm, int wn, int lane) {
    const int ar = (lane & 7) + ((lane >> 3) & 1) * 8;
    const int ak = ((lane >> 4) & 1) * 16;
    const int br = (lane & 7) + ((lane >> 4) & 1) * 8;
    const int bk = ((lane >> 3) & 1) * 16;
    const uint32_t a_base = As + (wm * 32 + ar) * apitch + ak;
    const uint32_t b_base = Bs + (wn * 32 + br) * bpitch + bk;
    #pragma unroll
    for (int ks = 0; ks < 8; ks++) {
        uint32_t af[2][4], bf[2][4];
        #pragma unroll
        for (int mt = 0; mt < 2; mt++) ldmx4(af[mt], a_base + mt * 16 * apitch + ks * 32);
        #pragma unroll
        for (int np = 0; np < 2; np++) ldmx4(bf[np], b_base + np * 16 * bpitch + ks * 32);
        #pragma unroll
        for (int mt = 0; mt < 2; mt++) {
            mma16816(acc[mt][0], af[mt], &bf[0][0]);
            mma16816(acc[mt][1], af[mt], &bf[0][2]);
            mma16816(acc[mt][2], af[mt], &bf[1][0]);
            mma16816(acc[mt][3], af[mt], &bf[1][2]);
        }
    }
}
#define ZERO32(acc) do { \
    _Pragma("unroll") for (int _i = 0; _i < 2; _i++) \
    _Pragma("unroll") for (int _j = 0; _j < 4; _j++) \
    _Pragma("unroll") for (int _k = 0; _k < 4; _k++) acc[_i][_j][_k] = 0.f; } while (0)

// ============== kernel 0: weight pre-conversion ==============
__global__ __launch_bounds__(256) void k_prep(const float* __restrict__ qkv_w,
                                              const float* __restrict__ proj_w,
                                              const float* __restrict__ fc1_w,
                                              const float* __restrict__ fc2_w) {
    int e = blockIdx.x * 256 + threadIdx.x;
    if (e < 49152) { int n = e >> 7, k = e & 127; g_wq[e] = __float2bfloat16(qkv_w[(size_t)k * 384 + n]); }
    if (e < 16384) { int n = e >> 7, k = e & 127; g_wp[e] = __float2bfloat16(proj_w[(size_t)k * 128 + n]); }
    if (e < 65536) {
        { int n = e >> 7, k = e & 127; g_w1[e] = __float2bfloat16(fc1_w[(size_t)k * 512 + n]); }
        { int n = e >> 9, k = e & 511; g_w2[e] = __float2bfloat16(fc2_w[(size_t)k * 128 + n]); }
    }
}

// k_wmsa smem offsets (bytes)
#define SM_XS 0         // LN'd X; later proj weights
#define SM_QS 34816
#define SM_KS 69632
#define SM_VS 104448
#define SM_OS 139264    // QKV weight buf1 during QKV; O during attention
#define SM_WB 174080    // QKV weight buf0
#define SM_BI 208896    // rel-pos bias float[4][448]
#define SM_WMSA 216064

// ============== kernel 1: fused W-MSA (unchanged from R6) ==============
__global__ __launch_bounds__(512) void k_wmsa(const float* __restrict__ x,
                                              const float* __restrict__ g1,
                                              const float* __restrict__ b1,
                                              const float* __restrict__ qkv_b,
                                              const float* __restrict__ rpb,
                                              const float* __restrict__ proj_b) {
    extern __shared__ char smc[];
    const uint32_t sb = smem_u32(smc);
    const int win = blockIdx.x;
    const int b = win >> 8, wi = win & 255, wh = wi >> 4, ww = wi & 15;
    const int t = threadIdx.x, lane = t & 31, wid = t >> 5;
    float* bsm = (float*)(smc + SM_BI);

    for (int i = t; i < 1764; i += 512) bsm[(i & 3) * 448 + (i >> 2)] = rpb[i];

    // --- LN1: warp-per-row ---
    {
        const int k4 = lane * 4;
        const float4 gv = *(const float4*)(g1 + k4);
        const float4 bv = *(const float4*)(b1 + k4);
        #pragma unroll
        for (int r8 = 0; r8 < 8; r8++) {
            int m = wid * 8 + r8;
            int r = (wh * 4 + (m >> 5) + SHIFT) & 63;
            int c = (ww * 32 + (m & 31) + SHIFT) & 511;
            float4 xv = *(const float4*)(x + ((size_t)(b * 64 + r) * 512 + c) * 128 + k4);
            float s = xv.x + xv.y + xv.z + xv.w;
            float ss = xv.x * xv.x + xv.y * xv.y + xv.z * xv.z + xv.w * xv.w;
            #pragma unroll
            for (int o = 16; o > 0; o >>= 1) {
                s += __shfl_xor_sync(0xFFFFFFFFu, s, o);
                ss += __shfl_xor_sync(0xFFFFFFFFu, ss, o);
            }
            float mean = s * (1.f / 128.f);
            float rstd = rsqrtf(ss * (1.f / 128.f) - mean * mean + 1e-5f);
            uint2 u;
            u.x = packbf((xv.x - mean) * rstd * gv.x + bv.x, (xv.y - mean) * rstd * gv.y + bv.y);
            u.y = packbf((xv.z - mean) * rstd * gv.z + bv.z, (xv.w - mean) * rstd * gv.w + bv.w);
            *(uint2*)(smc + SM_XS + m * PITCH + k4 * 2) = u;
        }
    }
    for (int i = t; i < 2048; i += 512) {
        int n = i >> 4, c16 = i & 15;
        CP16(sb + SM_WB + n * PITCH + c16 * 16, g_wq + (size_t)n * 128 + c16 * 8);
    }
    CP_COMMIT();
    __syncthreads();

    // --- QKV GEMMs, double-buffered weights ---
    const int wm = wid >> 2, wn = wid & 3;
    const uint32_t wbuf[2] = { sb + SM_WB, sb + SM_OS };
    for (int ct = 0; ct < 3; ct++) {
        if (ct < 2) {
            uint32_t dst = wbuf[(ct + 1) & 1];
            for (int i = t; i < 2048; i += 512) {
                int n = i >> 4, c16 = i & 15;
                CP16(dst + n * PITCH + c16 * 16, g_wq + (size_t)((ct + 1) * 128 + n) * 128 + c16 * 8);
            }
            CP_COMMIT();
            CP_WAIT(1);
        } else {
            CP_WAIT(0);
        }
        __syncthreads();
        float acc[2][4][4];
        ZERO32(acc);
        warp_mma32(sb + SM_XS, PITCH, wbuf[ct & 1], PITCH, acc, wm, wn, lane);

        const int dsto = (ct == 0) ? SM_QS : ((ct == 1) ? SM_KS : SM_VS);
        const float scl = (ct == 0) ? SCALE : 1.f;
        float bb[4][2];
        #pragma unroll
        for (int j = 0; j < 4; j++) {
            int col = wn * 32 + j * 8 + (lane & 3) * 2;
            bb[j][0] = qkv_b[ct * 128 + col];
            bb[j][1] = qkv_b[ct * 128 + col + 1];
        }
        #pragma unroll
        for (int mt = 0; mt < 2; mt++) {
            #pragma unroll
            for (int half = 0; half < 2; half++) {
                int row = wm * 32 + mt * 16 + (lane >> 2) + half * 8;
                #pragma unroll
                for (int j = 0; j < 4; j++) {
                    int col = wn * 32 + j * 8 + (lane & 3) * 2;
                    *(uint32_t*)(smc + dsto + row * PITCH + col * 2) =
                        packbf((acc[mt][j][half * 2 + 0] + bb[j][0]) * scl,
                               (acc[mt][j][half * 2 + 1] + bb[j][1]) * scl);
                }
            }
        }
        __syncthreads();
    }

    // prefetch proj weights into XS (X is dead now)
    for (int i = t; i < 2048; i += 512) {
        int n = i >> 4, c16 = i & 15;
        CP16(sb + SM_XS + n * PITCH + c16 * 16, g_wp + (size_t)n * 128 + c16 * 8);
    }
    CP_COMMIT();

    // --- attention ---
    const int ar = (lane & 7) + ((lane >> 3) & 1) * 8;
    const int ak = ((lane >> 4) & 1) * 16;
    const int br = (lane & 7) + ((lane >> 4) & 1) * 8;
    const int bk = ((lane >> 3) & 1) * 16;
    const bool edge = (wh == 15) || (ww == 15);

    #pragma unroll
    for (int it = 0; it < 2; it++) {
        const int task = wid + it * 16;
        const int h = task >> 3, g = task & 7;
        const int row0 = 16 * g + (lane >> 2), row1 = row0 + 8;
        const int ib0 = (row0 >> 5) * 63 + (row0 & 31) + 220;
        const int ib1 = (row1 >> 5) * 63 + (row1 & 31) + 220;

        // S = Q K^T
        float sacc[8][2][4];
        #pragma unroll
        for (int np = 0; np < 8; np++)
            #pragma unroll
            for (int s2 = 0; s2 < 2; s2++)
                #pragma unroll
                for (int c = 0; c < 4; c++) sacc[np][s2][c] = 0.f;
        {
            const uint32_t a0 = sb + SM_QS + (16 * g + ar) * PITCH + 64 * h + ak;
            const uint32_t b0 = sb + SM_KS + br * PITCH + 64 * h + bk;
            uint32_t af[2][4];
            ldmx4(af[0], a0);
            ldmx4(af[1], a0 + 32);
            #pragma unroll
            for (int np = 0; np < 8; np++) {
                uint32_t bf0[4], bf1[4];
                ldmx4(bf0, b0 + np * 16 * PITCH);
                ldmx4(bf1, b0 + np * 16 * PITCH + 32);
                mma16816(sacc[np][0], af[0], &bf0[0]);
                mma16816(sacc[np][1], af[0], &bf0[2]);
                mma16816(sacc[np][0], af[1], &bf1[0]);
                mma16816(sacc[np][1], af[1], &bf1[2]);
            }
        }

        // softmax (no max) -> P in registers as A-fragments
        const float* bh = bsm + h * 448;
        uint32_t ap[8][4];
        float rs0 = 0.f, rs1 = 0.f;
        if (!edge) {
            #pragma unroll
            for (int np = 0; np < 8; np++) {
                #pragma unroll
                for (int s2 = 0; s2 < 2; s2++) {
                    int col = np * 16 + s2 * 8 + (lane & 3) * 2;
                    int jo = (col >> 5) * 63 + (col & 31);
                    float p00 = __expf(sacc[np][s2][0] + bh[ib0 - jo]);
                    float p01 = __expf(sacc[np][s2][1] + bh[ib0 - jo - 1]);
                    float p10 = __expf(sacc[np][s2][2] + bh[ib1 - jo]);
                    float p11 = __expf(sacc[np][s2][3] + bh[ib1 - jo - 1]);
                    rs0 += p00 + p01;
                    rs1 += p10 + p11;
                    ap[np][s2 * 2 + 0] = packbf(p00, p01);
                    ap[np][s2 * 2 + 1] = packbf(p10, p11);
                }
            }
        } else {
            const int rgrp0 = ((wh < 15) ? 0 : (((row0 >> 5) < 2) ? 1 : 2)) * 3
                            + ((ww < 15) ? 0 : (((row0 & 31) < 30) ? 1 : 2));
            const int rgrp1 = ((wh < 15) ? 0 : (((row1 >> 5) < 2) ? 1 : 2)) * 3
                            + ((ww < 15) ? 0 : (((row1 & 31) < 30) ? 1 : 2));
            #pragma unroll
            for (int np = 0; np < 8; np++) {
                #pragma unroll
                for (int s2 = 0; s2 < 2; s2++) {
                    int col = np * 16 + s2 * 8 + (lane & 3) * 2;
                    int jh = col >> 5, jw = col & 31;
                    int cg0 = ((wh < 15) ? 0 : ((jh < 2) ? 1 : 2)) * 3
                            + ((ww < 15) ? 0 : ((jw < 30) ? 1 : 2));
                    int cg1 = ((wh < 15) ? 0 : ((jh < 2) ? 1 : 2)) * 3
                            + ((ww < 15) ? 0 : ((jw + 1 < 30) ? 1 : 2));
                    int jo = jh * 63 + jw;
                    float p00 = __expf(sacc[np][s2][0] + bh[ib0 - jo] + ((cg0 != rgrp0) ? -100.f : 0.f));
                    float p01 = __expf(sacc[np][s2][1] + bh[ib0 - jo - 1] + ((cg1 != rgrp0) ? -100.f : 0.f));
                    float p10 = __expf(sacc[np][s2][2] + bh[ib1 - jo] + ((cg0 != rgrp1) ? -100.f : 0.f));
                    float p11 = __expf(sacc[np][s2][3] + bh[ib1 - jo - 1] + ((cg1 != rgrp1) ? -100.f : 0.f));
                    rs0 += p00 + p01;
                    rs1 += p10 + p11;
                    ap[np][s2 * 2 + 0] = packbf(p00, p01);
                    ap[np][s2 * 2 + 1] = packbf(p10, p11);
                }
            }
        }
        rs0 += __shfl_xor_sync(0xFFFFFFFFu, rs0, 1);
        rs0 += __shfl_xor_sync(0xFFFFFFFFu, rs0, 2);
        rs1 += __shfl_xor_sync(0xFFFFFFFFu, rs1, 1);
        rs1 += __shfl_xor_sync(0xFFFFFFFFu, rs1, 2);
        const float inv0 = 1.f / rs0, inv1 = 1.f / rs1;

        // O = P V
        float oacc[4][4];
        #pragma unroll
        for (int j = 0; j < 4; j++)
            #pragma unroll
            for (int c = 0; c < 4; c++) oacc[j][c] = 0.f;
        #pragma unroll
        for (int ks = 0; ks < 8; ks++) {
            uint32_t va = sb + SM_VS + (16 * ks + (lane & 15)) * PITCH + 64 * h
                        + ((lane >> 4) & 1) * 16;
            uint32_t bv0[4], bv1[4];
            ldmx4t(bv0, va);
            ldmx4t(bv1, va + 32);
            mma16816(oacc[0], ap[ks], &bv0[0]);
            mma16816(oacc[1], ap[ks], &bv0[2]);
            mma16816(oacc[2], ap[ks], &bv1[0]);
            mma16816(oacc[3], ap[ks], &bv1[2]);
        }
        #pragma unroll
        for (int j = 0; j < 4; j++) {
            int col = 32 * h + j * 8 + (lane & 3) * 2;
            *(uint32_t*)(smc + SM_OS + row0 * PITCH + col * 2) =
                packbf(oacc[j][0] * inv0, oacc[j][1] * inv0);
            *(uint32_t*)(smc + SM_OS + row1 * PITCH + col * 2) =
                packbf(oacc[j][2] * inv1, oacc[j][3] * inv1);
        }
    }
    CP_WAIT(0);
    __syncthreads();

    // --- proj + window reverse + residual ---
    float acc[2][4][4];
    ZERO32(acc);
    warp_mma32(sb + SM_OS, PITCH, sb + SM_XS, PITCH, acc, wm, wn, lane);
    #pragma unroll
    for (int mt = 0; mt < 2; mt++) {
        #pragma unroll
        for (int half = 0; half < 2; half++) {
            int row = wm * 32 + mt * 16 + (lane >> 2) + half * 8;
            int r = (wh * 4 + (row >> 5) + SHIFT) & 63;
            int c = (ww * 32 + (row & 31) + SHIFT) & 511;
            size_t base = ((size_t)(b * 64 + r) * 512 + c) * 128;
            #pragma unroll
            for (int j = 0; j < 4; j++) {
                int n = wn * 32 + j * 8 + (lane & 3) * 2;
                float2 xr = *(const float2*)(x + base + n);
                float2 v;
                v.x = xr.x + acc[mt][j][half * 2 + 0] + proj_b[n];
                v.y = xr.y + acc[mt][j][half * 2 + 1] + proj_b[n + 1];
                *(float2*)(g_x1 + base + n) = v;
            }
        }
    }
}

// k_mlp smem: X (256x272) | Hc (256x272) | WA | WB
#define MM_X  0
#define MM_H  69632
#define MM_WA 139264
#define MM_WB 174080
#define SM_MLP3 208896

// ============== kernel 2: fused MLP, 256 tokens/CTA, fc1->fc2 per H-chunk ==============
__global__ __launch_bounds__(512) void k_mlp(const float* __restrict__ g2,
                                             const float* __restrict__ b2,
                                             const float* __restrict__ fc1_b,
                                             const float* __restrict__ fc2_b,
                                             float* __restrict__ out) {
    extern __shared__ char smc[];
    const uint32_t sb = smem_u32(smc);
    const uint32_t Xs = sb + MM_X, Hs = sb + MM_H, WA = sb + MM_WA, WBu = sb + MM_WB;
    const int tile = blockIdx.x;
    const int t = threadIdx.x, lane = t & 31, wid = t >> 5;
    const int wm = wid >> 2, wn = wid & 3;

    // prefetch fc1 chunk 0 -> WA
    for (int i = t; i < 2048; i += 512) {
        int n = i >> 4, c16 = i & 15;
        CP16(WA + n * PITCH + c16 * 16, g_w1 + (size_t)n * 128 + c16 * 8);
    }
    CP_COMMIT();

    // LN2: warp handles 16 rows
    {
        const int k4 = lane * 4;
        const float4 gv = *(const float4*)(g2 + k4);
        const float4 bv = *(const float4*)(b2 + k4);
        #pragma unroll
        for (int r8 = 0; r8 < 16; r8++) {
            int m = wid * 16 + r8;
            float4 xv = *(const float4*)(g_x1 + ((size_t)tile * 256 + m) * 128 + k4);
            float s = xv.x + xv.y + xv.z + xv.w;
            float ss = xv.x * xv.x + xv.y * xv.y + xv.z * xv.z + xv.w * xv.w;
            #pragma unroll
            for (int o = 16; o > 0; o >>= 1) {
                s += __shfl_xor_sync(0xFFFFFFFFu, s, o);
                ss += __shfl_xor_sync(0xFFFFFFFFu, ss, o);
            }
            float mean = s * (1.f / 128.f);
            float rstd = rsqrtf(ss * (1.f / 128.f) - mean * mean + 1e-5f);
            uint2 u;
            u.x = packbf((xv.x - mean) * rstd * gv.x + bv.x, (xv.y - mean) * rstd * gv.y + bv.y);
            u.y = packbf((xv.z - mean) * rstd * gv.z + bv.z, (xv.w - mean) * rstd * gv.w + bv.w);
            *(uint2*)(smc + MM_X + m * PITCH + k4 * 2) = u;
        }
    }

    const int ar = (lane & 7) + ((lane >> 3) & 1) * 8;
    const int ak = ((lane >> 4) & 1) * 16;
    const int br = (lane & 7) + ((lane >> 4) & 1) * 8;
    const int bk = ((lane >> 3) & 1) * 16;

    float acc2[4][4][4];
    #pragma unroll
    for (int i = 0; i < 4; i++)
        #pragma unroll
        for (int j = 0; j < 4; j++)
            #pragma unroll
            for (int k = 0; k < 4; k++) acc2[i][j][k] = 0.f;

    for (int ct = 0; ct < 4; ct++) {
        CP_WAIT(0);            // W1(ct) done (own); barrier publishes cross-thread
        __syncthreads();       // also: X ready (ct=0); WB free (ct>0)
        // issue W2(ct) -> WB (overlaps fc1)
        for (int i = t; i < 2048; i += 512) {
            int n = i >> 4, c16 = i & 15;
            CP16(WBu + n * PITCH + c16 * 16, g_w2 + (size_t)n * 512 + ct * 128 + c16 * 8);
        }
        CP_COMMIT();

        // ---- fc1 (ct): 2 M-subpasses of 32x32 per warp ----
        #pragma unroll
        for (int s = 0; s < 2; s++) {
            float a1[2][4][4];
            ZERO32(a1);
            const uint32_t a_base = Xs + (wm * 64 + s * 32 + ar) * PITCH + ak;
            const uint32_t b_base = WA + (wn * 32 + br) * PITCH + bk;
            #pragma unroll
            for (int ks = 0; ks < 8; ks++) {
                uint32_t af[2][4], bf[2][4];
                #pragma unroll
                for (int mt = 0; mt < 2; mt++) ldmx4(af[mt], a_base + mt * 16 * PITCH + ks * 32);
                #pragma unroll
                for (int np = 0; np < 2; np++) ldmx4(bf[np], b_base + np * 16 * PITCH + ks * 32);
                #pragma unroll
                for (int mt = 0; mt < 2; mt++) {
                    mma16816(a1[mt][0], af[mt], &bf[0][0]);
                    mma16816(a1[mt][1], af[mt], &bf[0][2]);
                    mma16816(a1[mt][2], af[mt], &bf[1][0]);
                    mma16816(a1[mt][3], af[mt], &bf[1][2]);
                }
            }
            #pragma unroll
            for (int mt = 0; mt < 2; mt++) {
                #pragma unroll
                for (int half = 0; half < 2; half++) {
                    int row = wm * 64 + s * 32 + mt * 16 + (lane >> 2) + half * 8;
                    #pragma unroll
                    for (int j = 0; j < 4; j++) {
                        int n = wn * 32 + j * 8 + (lane & 3) * 2;
                        float v0 = a1[mt][j][half * 2 + 0] + fc1_b[ct * 128 + n];
                        float v1 = a1[mt][j][half * 2 + 1] + fc1_b[ct * 128 + n + 1];
                        float e0 = 0.5f * v0 * (1.f + erff(v0 * 0.70710678118654752f));
                        float e1 = 0.5f * v1 * (1.f + erff(v1 * 0.70710678118654752f));
                        *(uint32_t*)(smc + MM_H + row * PITCH + n * 2) = packbf(e0, e1);
                    }
                }
            }
        }
        CP_WAIT(0);            // W2(ct) done (own)
        __syncthreads();       // Hc published; W2 published; WA free
        if (ct < 3) {          // prefetch W1(ct+1) -> WA (overlaps fc2)
            for (int i = t; i < 2048; i += 512) {
                int n = i >> 4, c16 = i & 15;
                CP16(WA + n * PITCH + c16 * 16,
                     g_w1 + (size_t)((ct + 1) * 128 + n) * 128 + c16 * 8);
            }
            CP_COMMIT();
        }

        // ---- fc2 (ct): acc2 += Hc @ W2c, warp tile 64x32 ----
        const uint32_t a2 = Hs + (wm * 64 + ar) * PITCH + ak;
        const uint32_t b2b = WBu + (wn * 32 + br) * PITCH + bk;
        #pragma unroll
        for (int ks = 0; ks < 8; ks++) {
            uint32_t af[4][4], bf[2][4];
            #pragma unroll
            for (int mt = 0; mt < 4; mt++) ldmx4(af[mt], a2 + mt * 16 * PITCH + ks * 32);
            #pragma unroll
            for (int np = 0; np < 2; np++) ldmx4(bf[np], b2b + np * 16 * PITCH + ks * 32);
            #pragma unroll
            for (int mt = 0; mt < 4; mt++) {
                mma16816(acc2[mt][0], af[mt], &bf[0][0]);
                mma16816(acc2[mt][1], af[mt], &bf[0][2]);
                mma16816(acc2[mt][2], af[mt], &bf[1][0]);
                mma16816(acc2[mt][3], af[mt], &bf[1][2]);
            }
        }
    }

    // ---- epilogue: residual + out ----
    #pragma unroll
    for (int mt = 0; mt < 4; mt++) {
        #pragma unroll
        for (int half = 0; half < 2; half++) {
            int row = wm * 64 + mt * 16 + (lane >> 2) + half * 8;
            const float* xr = g_x1 + ((size_t)tile * 256 + row) * 128;
            float* orow = out + ((size_t)tile * 256 + row) * 128;
            #pragma unroll
            for (int j = 0; j < 4; j++) {
                int n = wn * 32 + j * 8 + (lane & 3) * 2;
                float2 rv = *(const float2*)(xr + n);
                float2 v;
                v.x = rv.x + acc2[mt][j][half * 2 + 0] + fc2_b[n];
                v.y = rv.y + acc2[mt][j][half * 2 + 1] + fc2_b[n + 1];
                *(float2*)(orow + n) = v;
            }
        }
    }
}

// ---------------- launcher ----------------
extern "C" void kernel_launch(void* const* d_in, const int* in_sizes, int n_in,
                              void* d_out, int out_size) {
    (void)in_sizes; (void)n_in; (void)out_size;
    const float* x      = (const float*)d_in[0];
    const float* g1     = (const float*)d_in[1];
    const float* b1     = (const float*)d_in[2];
    const float* qkv_w  = (const float*)d_in[3];
    const float* qkv_b  = (const float*)d_in[4];
    const float* rpb    = (const float*)d_in[5];
    const float* proj_w = (const float*)d_in[6];
    const float* proj_b = (const float*)d_in[7];
    const float* g2     = (const float*)d_in[8];
    const float* b2     = (const float*)d_in[9];
    const float* fc1_w  = (const float*)d_in[10];
    const float* fc1_b  = (const float*)d_in[11];
    const float* fc2_w  = (const float*)d_in[12];
    const float* fc2_b  = (const float*)d_in[13];
    float* out = (float*)d_out;

    cudaFuncSetAttribute(k_wmsa, cudaFuncAttributeMaxDynamicSharedMemorySize, SM_WMSA);
    cudaFuncSetAttribute(k_mlp,  cudaFuncAttributeMaxDynamicSharedMemorySize, SM_MLP3);

    k_prep<<<256, 256>>>(qkv_w, proj_w, fc1_w, fc2_w);
    k_wmsa<<<NWTOT, 512, SM_WMSA>>>(x, g1, b1, qkv_b, rpb, proj_b);
    k_mlp<<<TOK / 256, 512, SM_MLP3>>>(g2, b2, fc1_b, fc2_b, out);
}